// round 4
// baseline (speedup 1.0000x reference)
#include <cuda_runtime.h>
#include <cuda_fp16.h>
#include <cstdint>

// ---------------- constants (problem-fixed) ----------------
#define NNODES 100000
#define DIN    128
#define HDIM   256
#define H2     512
#define NLAYER 4
#define NGRAPH 512
#define BN_EPS 1e-5f

// ---------------- scratch (device globals; no allocation allowed) ----------------
__device__ float g_h[NNODES * HDIM];      // current node features
__device__ float g_agg[NNODES * HDIM];    // (1+eps)h + scatter
__device__ float g_z1[NNODES * H2];       // MLP hidden
__device__ float g_z2[NNODES * HDIM];     // MLP out (pre-BN)
__device__ float g_stats[2 * HDIM];       // [sums | sumsq]
__device__ float g_pool[NGRAPH * HDIM];   // per-graph sums
__device__ float g_cnt[NGRAPH];           // per-graph counts

// converted weights: transposed [N][K], single fp16
#define WIN_OFF  0
#define W1_OFF   (256 * 128)
#define W2_OFF   (W1_OFF + NLAYER * 512 * 256)
#define WT_TOTAL (W2_OFF + NLAYER * 256 * 512)
__device__ __align__(16) __half g_wh[WT_TOTAL];

// ---------------- helpers ----------------
__device__ __forceinline__ uint32_t smem_u32(const void* p) {
    uint32_t a;
    asm("{ .reg .u64 t; cvta.to.shared.u64 t, %1; cvt.u32.u64 %0, t; }" : "=r"(a) : "l"(p));
    return a;
}
__device__ __forceinline__ uint32_t pkh(__half a, __half b) {
    __half2 t; t.x = a; t.y = b;
    return *reinterpret_cast<uint32_t*>(&t);
}
__device__ __forceinline__ void ldm4(uint32_t* r, uint32_t addr) {
    asm volatile("ldmatrix.sync.aligned.m8n8.x4.shared.b16 {%0,%1,%2,%3}, [%4];"
                 : "=r"(r[0]), "=r"(r[1]), "=r"(r[2]), "=r"(r[3]) : "r"(addr));
}
__device__ __forceinline__ void mma16816(float* c, const uint32_t* a, const uint32_t* b) {
    asm volatile("mma.sync.aligned.m16n8k16.row.col.f32.f16.f16.f32 "
                 "{%0,%1,%2,%3}, {%4,%5,%6,%7}, {%8,%9}, {%0,%1,%2,%3};"
                 : "+f"(c[0]), "+f"(c[1]), "+f"(c[2]), "+f"(c[3])
                 : "r"(a[0]), "r"(a[1]), "r"(a[2]), "r"(a[3]), "r"(b[0]), "r"(b[1]));
}

// smem stage layout: Ah(10240) Al(10240) B(10240); 80B rows
#define ROWB  80
#define T_AH  0
#define T_AL  10240
#define T_B   20480
#define STAGE 30720
#define SMEMB (2 * STAGE)

// ---------------- tensor-core GEMM via mma.sync fp16, A hi/lo split ----------------
// C[M,N] = act(A[M,K]fp32 @ W[K,N] + bias); W pre-rounded fp16 [N][K].
// Block tile 128x128, K-chunk 32, 256 threads (warp tile 32x64), double-buffered.
// EPI: 1 = bias+relu; 2 = bias+relu -> C, and C2 = (1+eps)*C; 3 = bias only + fused BN stats.
template <int EPI>
__global__ __launch_bounds__(256, 1)
void tc_gemm(const float* __restrict__ A, const __half* __restrict__ Bh,
             const float* __restrict__ bias, float* __restrict__ C, float* __restrict__ C2,
             const float* __restrict__ epsp, float* __restrict__ stats,
             int M, int N, int K)
{
    extern __shared__ __align__(16) char smraw[];
    const uint32_t sb = smem_u32(smraw);

    const int tid = threadIdx.x;
    const int lane = tid & 31, wid = tid >> 5;
    const int wm = (wid & 3) * 32;       // warp M offset (4 warps)
    const int wn = (wid >> 2) * 64;      // warp N offset (2 warps)
    const int bm = blockIdx.y * 128, bn = blockIdx.x * 128;
    const int nc = K / 32;

    float acc[2][8][4];
#pragma unroll
    for (int i = 0; i < 2; i++)
#pragma unroll
        for (int j = 0; j < 8; j++)
#pragma unroll
            for (int q = 0; q < 4; q++) acc[i][j][q] = 0.f;

    // A gmem mapping: 2 threads per row, 16 floats each
    const int arow = tid >> 1;
    const int acol = (tid & 1) * 16;
    int rg = bm + arow; if (rg >= M) rg = M - 1;
    const float* aptr = A + (size_t)rg * K + acol;
    const uint32_t aoff = (uint32_t)arow * ROWB + (uint32_t)acol * 2;

    float4 ar[4];

    // ---- prologue: chunk 0 ----
#pragma unroll
    for (int j = 0; j < 4; j++) ar[j] = __ldg((const float4*)(aptr + 4 * j));
#pragma unroll
    for (int i = 0; i < 2; i++) {
        int cc = tid + 256 * i;
        int row = cc >> 2, seg = cc & 3;
        const __half* src = Bh + (size_t)(bn + row) * K + seg * 8;
        uint32_t dst = sb + T_B + (uint32_t)row * ROWB + seg * 16;
        asm volatile("cp.async.ca.shared.global [%0], [%1], 16;" :: "r"(dst), "l"(src));
    }
    asm volatile("cp.async.commit_group;");
    {
        uint32_t dh = sb + T_AH + aoff, dl = sb + T_AL + aoff;
#pragma unroll
        for (int j = 0; j < 4; j++) {
            float4 v = ar[j];
            __half hx = __float2half(v.x), hy = __float2half(v.y);
            __half hz = __float2half(v.z), hw = __float2half(v.w);
            uint32_t h0 = pkh(hx, hy), h1 = pkh(hz, hw);
            uint32_t l0 = pkh(__float2half(v.x - __half2float(hx)),
                              __float2half(v.y - __half2float(hy)));
            uint32_t l1 = pkh(__float2half(v.z - __half2float(hz)),
                              __float2half(v.w - __half2float(hw)));
            asm volatile("st.shared.v2.b32 [%0], {%1,%2};" :: "r"(dh + j * 8), "r"(h0), "r"(h1) : "memory");
            asm volatile("st.shared.v2.b32 [%0], {%1,%2};" :: "r"(dl + j * 8), "r"(l0), "r"(l1) : "memory");
        }
    }
    asm volatile("cp.async.wait_group 0;");
    __syncthreads();

    // fragment address components
    const uint32_t a_ro = (uint32_t)(lane & 15) * ROWB + (uint32_t)(lane >> 4) * 16;
    const int brow = (lane & 7) + ((lane >> 4) << 3);
    const uint32_t b_ko = (uint32_t)((lane >> 3) & 1) * 16;

    for (int c = 0; c < nc; c++) {
        const uint32_t st0 = sb + (uint32_t)(c & 1) * STAGE;
        const uint32_t stn = sb + (uint32_t)((c + 1) & 1) * STAGE;
        const bool more = (c + 1 < nc);

        if (more) {
#pragma unroll
            for (int j = 0; j < 4; j++) ar[j] = __ldg((const float4*)(aptr + (c + 1) * 32 + 4 * j));
#pragma unroll
            for (int i = 0; i < 2; i++) {
                int cc = tid + 256 * i;
                int row = cc >> 2, seg = cc & 3;
                const __half* src = Bh + (size_t)(bn + row) * K + (c + 1) * 32 + seg * 8;
                uint32_t dst = stn + T_B + (uint32_t)row * ROWB + seg * 16;
                asm volatile("cp.async.ca.shared.global [%0], [%1], 16;" :: "r"(dst), "l"(src));
            }
            asm volatile("cp.async.commit_group;");
        }

        // ---- compute chunk c ----
#pragma unroll
        for (int ks = 0; ks < 2; ks++) {
            uint32_t ah[2][4], al[2][4], bh[4][4];
            uint32_t abase = st0 + ks * 32 + a_ro + (uint32_t)wm * ROWB;
            ldm4(ah[0], abase + T_AH);
            ldm4(ah[1], abase + T_AH + 16 * ROWB);
            ldm4(al[0], abase + T_AL);
            ldm4(al[1], abase + T_AL + 16 * ROWB);
#pragma unroll
            for (int g = 0; g < 4; g++) {
                uint32_t bbase = st0 + ks * 32 + b_ko + (uint32_t)(wn + g * 16 + brow) * ROWB;
                ldm4(bh[g], bbase + T_B);
            }
            // sweep 1: Ah x B
#pragma unroll
            for (int mt = 0; mt < 2; mt++)
#pragma unroll
                for (int g = 0; g < 4; g++) {
                    mma16816(acc[mt][2 * g],     ah[mt], &bh[g][0]);
                    mma16816(acc[mt][2 * g + 1], ah[mt], &bh[g][2]);
                }
            // sweep 2: Al x B
#pragma unroll
            for (int mt = 0; mt < 2; mt++)
#pragma unroll
                for (int g = 0; g < 4; g++) {
                    mma16816(acc[mt][2 * g],     al[mt], &bh[g][0]);
                    mma16816(acc[mt][2 * g + 1], al[mt], &bh[g][2]);
                }
        }

        if (more) {
            uint32_t dh = stn + T_AH + aoff, dl = stn + T_AL + aoff;
#pragma unroll
            for (int j = 0; j < 4; j++) {
                float4 v = ar[j];
                __half hx = __float2half(v.x), hy = __float2half(v.y);
                __half hz = __float2half(v.z), hw = __float2half(v.w);
                uint32_t h0 = pkh(hx, hy), h1 = pkh(hz, hw);
                uint32_t l0 = pkh(__float2half(v.x - __half2float(hx)),
                                  __float2half(v.y - __half2float(hy)));
                uint32_t l1 = pkh(__float2half(v.z - __half2float(hz)),
                                  __float2half(v.w - __half2float(hw)));
                asm volatile("st.shared.v2.b32 [%0], {%1,%2};" :: "r"(dh + j * 8), "r"(h0), "r"(h1) : "memory");
                asm volatile("st.shared.v2.b32 [%0], {%1,%2};" :: "r"(dl + j * 8), "r"(l0), "r"(l1) : "memory");
            }
        }
        asm volatile("cp.async.wait_group 0;");
        __syncthreads();
    }

    // ---- epilogue ----
    float* ssum = reinterpret_cast<float*>(smraw);        // [128]
    float* ssq  = reinterpret_cast<float*>(smraw) + 128;  // [128]
    if (EPI == 3) {
        if (tid < 256) reinterpret_cast<float*>(smraw)[tid] = 0.f;
        __syncthreads();
    }

    float emul = 0.f;
    if (EPI == 2) emul = 1.0f + __ldg(epsp);
#pragma unroll
    for (int mt = 0; mt < 2; mt++) {
        int r0 = bm + wm + mt * 16 + (lane >> 2);
        int r1 = r0 + 8;
#pragma unroll
        for (int nt = 0; nt < 8; nt++) {
            int col = bn + wn + nt * 8 + (lane & 3) * 2;
            float2 bv = *reinterpret_cast<const float2*>(&bias[col]);
            float v0 = acc[mt][nt][0] + bv.x;
            float v1 = acc[mt][nt][1] + bv.y;
            float v2 = acc[mt][nt][2] + bv.x;
            float v3 = acc[mt][nt][3] + bv.y;
            if (EPI == 1 || EPI == 2) {
                v0 = fmaxf(v0, 0.f); v1 = fmaxf(v1, 0.f);
                v2 = fmaxf(v2, 0.f); v3 = fmaxf(v3, 0.f);
            }
            bool k0 = r0 < M, k1 = r1 < M;
            if (k0) {
                *reinterpret_cast<float2*>(&C[(size_t)r0 * N + col]) = make_float2(v0, v1);
                if (EPI == 2)
                    *reinterpret_cast<float2*>(&C2[(size_t)r0 * N + col]) = make_float2(emul * v0, emul * v1);
            }
            if (k1) {
                *reinterpret_cast<float2*>(&C[(size_t)r1 * N + col]) = make_float2(v2, v3);
                if (EPI == 2)
                    *reinterpret_cast<float2*>(&C2[(size_t)r1 * N + col]) = make_float2(emul * v2, emul * v3);
            }
            if (EPI == 3) {
                int lc = wn + nt * 8 + (lane & 3) * 2;
                float a0 = (k0 ? v0 : 0.f) + (k1 ? v2 : 0.f);
                float a1 = (k0 ? v1 : 0.f) + (k1 ? v3 : 0.f);
                float q0 = (k0 ? v0 * v0 : 0.f) + (k1 ? v2 * v2 : 0.f);
                float q1 = (k0 ? v1 * v1 : 0.f) + (k1 ? v3 * v3 : 0.f);
                atomicAdd(&ssum[lc], a0);
                atomicAdd(&ssum[lc + 1], a1);
                atomicAdd(&ssq[lc], q0);
                atomicAdd(&ssq[lc + 1], q1);
            }
        }
    }
    if (EPI == 3) {
        __syncthreads();
        if (tid < 128) {
            atomicAdd(&stats[bn + tid], ssum[tid]);
            atomicAdd(&stats[HDIM + bn + tid], ssq[tid]);
        }
    }
}

// ---------------- all-weight conversion: transpose + fp16 round (one launch) ----------------
#define NW_IN (128 * 256)
#define NW_1  (256 * 512)
#define NW_2  (512 * 256)
__global__ void conv_w_all(const float* __restrict__ W_in, const float* __restrict__ W1,
                           const float* __restrict__ W2, __half* __restrict__ wh)
{
    int idx = blockIdx.x * blockDim.x + threadIdx.x;
    if (idx < NW_IN) {
        int n = idx / 128, k = idx % 128;
        wh[WIN_OFF + idx] = __float2half(W_in[(size_t)k * 256 + n]);
    } else if (idx < NW_IN + NLAYER * NW_1) {
        int t = idx - NW_IN;
        int l = t / NW_1, r = t % NW_1;
        int n = r / 256, k = r % 256;
        wh[W1_OFF + t] = __float2half(W1[(size_t)l * NW_1 + (size_t)k * 512 + n]);
    } else if (idx < NW_IN + NLAYER * (NW_1 + NW_2)) {
        int t = idx - NW_IN - NLAYER * NW_1;
        int l = t / NW_2, r = t % NW_2;
        int n = r / 512, k = r % 512;
        wh[W2_OFF + t] = __float2half(W2[(size_t)l * NW_2 + (size_t)k * 256 + n]);
    }
}

// ---------------- edge scatter: agg[dst] += h[src] ----------------
__global__ void scatter_kernel(const float* __restrict__ h, const int* __restrict__ src,
                               const int* __restrict__ dst, float* __restrict__ agg, int E)
{
    int idx = blockIdx.x * blockDim.x + threadIdx.x;
    int e = idx >> 6;
    if (e >= E) return;
    int c4 = (idx & 63) << 2;
    int s = __ldg(&src[e]);
    int d = __ldg(&dst[e]);
    float4 v = __ldg(reinterpret_cast<const float4*>(&h[(size_t)s * HDIM + c4]));
    float* o = &agg[(size_t)d * HDIM + c4];
    atomicAdd(o + 0, v.x);
    atomicAdd(o + 1, v.y);
    atomicAdd(o + 2, v.z);
    atomicAdd(o + 3, v.w);
}

// ---------------- BN apply + relu ----------------
// POOL=0: write h and agg=(1+eps_next)*h. POOL=1: atomic-add into per-graph pool only.
template <int POOL>
__global__ void bn_apply_kernel(const float4* __restrict__ z, const float* __restrict__ stats,
                                const float* __restrict__ gamma, const float* __restrict__ beta,
                                const float* __restrict__ epsn,
                                float4* __restrict__ h, float4* __restrict__ agg,
                                const int* __restrict__ batch, float* __restrict__ pool,
                                int total4)
{
    int i = blockIdx.x * blockDim.x + threadIdx.x;
    if (i >= total4) return;
    int c = (i << 2) & (HDIM - 1);
    const float invN = 1.0f / (float)NNODES;
    float4 s = *reinterpret_cast<const float4*>(&stats[c]);
    float4 q = *reinterpret_cast<const float4*>(&stats[HDIM + c]);
    float4 g = *reinterpret_cast<const float4*>(&gamma[c]);
    float4 b = *reinterpret_cast<const float4*>(&beta[c]);
    float4 zv = z[i];
    float4 r;
    {
        float mu = s.x * invN, var = q.x * invN - mu * mu;
        r.x = fmaxf((zv.x - mu) * (g.x * rsqrtf(var + BN_EPS)) + b.x, 0.f);
    }
    {
        float mu = s.y * invN, var = q.y * invN - mu * mu;
        r.y = fmaxf((zv.y - mu) * (g.y * rsqrtf(var + BN_EPS)) + b.y, 0.f);
    }
    {
        float mu = s.z * invN, var = q.z * invN - mu * mu;
        r.z = fmaxf((zv.z - mu) * (g.z * rsqrtf(var + BN_EPS)) + b.z, 0.f);
    }
    {
        float mu = s.w * invN, var = q.w * invN - mu * mu;
        r.w = fmaxf((zv.w - mu) * (g.w * rsqrtf(var + BN_EPS)) + b.w, 0.f);
    }
    if (POOL == 0) {
        h[i] = r;
        float e = 1.0f + __ldg(epsn);
        float4 a; a.x = e * r.x; a.y = e * r.y; a.z = e * r.z; a.w = e * r.w;
        agg[i] = a;
    } else {
        int node = i >> 6;
        int gidx = __ldg(&batch[node]);
        float* o = &pool[(size_t)gidx * HDIM + c];
        atomicAdd(o + 0, r.x);
        atomicAdd(o + 1, r.y);
        atomicAdd(o + 2, r.z);
        atomicAdd(o + 3, r.w);
    }
}

// ---------------- per-graph node counts ----------------
__global__ void count_kernel(const int* __restrict__ batch, float* __restrict__ cnt, int n)
{
    int i = blockIdx.x * blockDim.x + threadIdx.x;
    if (i < n) atomicAdd(&cnt[__ldg(&batch[i])], 1.0f);
}

// ---------------- predictor head ----------------
__global__ void head_kernel(const float* __restrict__ pooled, const float* __restrict__ cnt,
                            const float* __restrict__ Wp1, const float* __restrict__ bp1,
                            const float* __restrict__ Wp2, const float* __restrict__ bp2,
                            float* __restrict__ out)
{
    __shared__ float sp[HDIM];
    __shared__ float red[128];
    int g = blockIdx.x;
    int tid = threadIdx.x;   // 128 threads
    float inv = 1.0f / fmaxf(__ldg(&cnt[g]), 1.0f);
    for (int k = tid; k < HDIM; k += 128)
        sp[k] = pooled[(size_t)g * HDIM + k] * inv;
    __syncthreads();

    float s = __ldg(&bp1[tid]);
#pragma unroll 4
    for (int k = 0; k < HDIM; k++)
        s = fmaf(sp[k], __ldg(&Wp1[k * 128 + tid]), s);
    s = fmaxf(s, 0.f);
    float t = s * __ldg(&Wp2[tid]);

    red[tid] = t;
    __syncthreads();
    for (int off = 64; off > 0; off >>= 1) {
        if (tid < off) red[tid] += red[tid + off];
        __syncthreads();
    }
    if (tid == 0) out[g] = red[0] + __ldg(&bp2[0]);
}

// ---------------- host launch ----------------
static void* sym_addr(const void* symbol)
{
    void* p = nullptr;
    cudaGetSymbolAddress(&p, symbol);
    return p;
}

extern "C" void kernel_launch(void* const* d_in, const int* in_sizes, int n_in,
                              void* d_out, int out_size)
{
    const float* x      = (const float*)d_in[0];
    const int*   ei     = (const int*)d_in[1];
    const int*   batch  = (const int*)d_in[2];
    const float* W_in   = (const float*)d_in[3];
    const float* b_in   = (const float*)d_in[4];
    const float* eps    = (const float*)d_in[5];
    const float* W1     = (const float*)d_in[6];
    const float* b1     = (const float*)d_in[7];
    const float* W2     = (const float*)d_in[8];
    const float* b2     = (const float*)d_in[9];
    const float* gamma  = (const float*)d_in[10];
    const float* beta   = (const float*)d_in[11];
    const float* Wp1    = (const float*)d_in[12];
    const float* bp1    = (const float*)d_in[13];
    const float* Wp2    = (const float*)d_in[14];
    const float* bp2    = (const float*)d_in[15];
    float* out = (float*)d_out;

    const int E = in_sizes[1] / 2;
    const int* src = ei;
    const int* dst = ei + E;

    float* h     = (float*)sym_addr(g_h);
    float* agg   = (float*)sym_addr(g_agg);
    float* z1    = (float*)sym_addr(g_z1);
    float* z2    = (float*)sym_addr(g_z2);
    float* stats = (float*)sym_addr(g_stats);
    float* pool  = (float*)sym_addr(g_pool);
    float* cnt   = (float*)sym_addr(g_cnt);
    __half* wh   = (__half*)sym_addr(g_wh);

    cudaFuncSetAttribute(tc_gemm<1>, cudaFuncAttributeMaxDynamicSharedMemorySize, SMEMB);
    cudaFuncSetAttribute(tc_gemm<2>, cudaFuncAttributeMaxDynamicSharedMemorySize, SMEMB);
    cudaFuncSetAttribute(tc_gemm<3>, cudaFuncAttributeMaxDynamicSharedMemorySize, SMEMB);

    const int M = NNODES;
    const int mt = (M + 127) / 128;    // 782
    const int totalH = M * HDIM;
    const int total4 = totalH / 4;

    // ---- weight prep (single launch) ----
    {
        int tot = NW_IN + NLAYER * (NW_1 + NW_2);
        conv_w_all<<<(tot + 255) / 256, 256>>>(W_in, W1, W2, wh);
    }

    // ---- input projection: h = relu(x@W_in + b_in), agg = (1+eps0)*h ----
    tc_gemm<2><<<dim3(2, mt), 256, SMEMB>>>(x, wh + WIN_OFF, b_in, h, agg, eps, nullptr,
                                            M, HDIM, DIN);

    for (int l = 0; l < NLAYER; l++) {
        // agg[dst] += h[src]
        {
            long long tot = (long long)E * 64;
            scatter_kernel<<<(int)((tot + 255) / 256), 256>>>(h, src, dst, agg, E);
        }
        // z1 = relu(agg @ W1_l + b1_l)
        tc_gemm<1><<<dim3(4, mt), 256, SMEMB>>>(agg, wh + W1_OFF + (size_t)l * H2 * HDIM,
                                                b1 + (size_t)l * H2, z1, nullptr, nullptr,
                                                nullptr, M, H2, HDIM);
        // z2 = z1 @ W2_l + b2_l (+ fused BN stats)
        cudaMemsetAsync(stats, 0, 2 * HDIM * sizeof(float));
        tc_gemm<3><<<dim3(2, mt), 256, SMEMB>>>(z1, wh + W2_OFF + (size_t)l * HDIM * H2,
                                                b2 + (size_t)l * HDIM, z2, nullptr, nullptr,
                                                stats, M, HDIM, H2);
        // BN apply + relu
        if (l + 1 < NLAYER) {
            bn_apply_kernel<0><<<(total4 + 255) / 256, 256>>>(
                (const float4*)z2, stats, gamma + (size_t)l * HDIM, beta + (size_t)l * HDIM,
                eps + (l + 1), (float4*)h, (float4*)agg, nullptr, nullptr, total4);
        } else {
            cudaMemsetAsync(pool, 0, NGRAPH * HDIM * sizeof(float));
            cudaMemsetAsync(cnt, 0, NGRAPH * sizeof(float));
            count_kernel<<<(M + 255) / 256, 256>>>(batch, cnt, M);
            bn_apply_kernel<1><<<(total4 + 255) / 256, 256>>>(
                (const float4*)z2, stats, gamma + (size_t)l * HDIM, beta + (size_t)l * HDIM,
                nullptr, nullptr, nullptr, batch, pool, total4);
        }
    }

    // ---- head ----
    head_kernel<<<NGRAPH, 128>>>(pool, cnt, Wp1, bp1, Wp2, bp2, out);
}

// round 5
// speedup vs baseline: 1.5701x; 1.5701x over previous
#include <cuda_runtime.h>
#include <cuda_fp16.h>
#include <cstdint>

// ---------------- constants (problem-fixed) ----------------
#define NNODES 100000
#define DIN    128
#define HDIM   256
#define H2     512
#define NLAYER 4
#define NGRAPH 512
#define BN_EPS 1e-5f

// ---------------- scratch (device globals; no allocation allowed) ----------------
__device__ float g_h[NNODES * HDIM];      // current node features
__device__ float g_agg[NNODES * HDIM];    // (1+eps)h + scatter
__device__ float g_z1[NNODES * H2];       // MLP hidden
__device__ float g_z2[NNODES * HDIM];     // MLP out (pre-BN)
__device__ float g_stats[2 * HDIM];       // [sums | sumsq]
__device__ float g_pool[NGRAPH * HDIM];   // per-graph sums
__device__ float g_cnt[NGRAPH];           // per-graph counts

// converted weights: transposed [N][K], single fp16
#define WIN_OFF  0
#define W1_OFF   (256 * 128)
#define W2_OFF   (W1_OFF + NLAYER * 512 * 256)
#define WT_TOTAL (W2_OFF + NLAYER * 256 * 512)
__device__ __align__(16) __half g_wh[WT_TOTAL];

// ---------------- helpers ----------------
__device__ __forceinline__ uint32_t smem_u32(const void* p) {
    uint32_t a;
    asm("{ .reg .u64 t; cvta.to.shared.u64 t, %1; cvt.u32.u64 %0, t; }" : "=r"(a) : "l"(p));
    return a;
}
__device__ __forceinline__ uint32_t pkh(__half a, __half b) {
    __half2 t; t.x = a; t.y = b;
    return *reinterpret_cast<uint32_t*>(&t);
}
__device__ __forceinline__ uint32_t sw64(uint32_t off) {
    return off ^ ((off >> 3) & 0x30);
}
__device__ __forceinline__ void ldm4(uint32_t* r, uint32_t addr) {
    asm volatile("ldmatrix.sync.aligned.m8n8.x4.shared.b16 {%0,%1,%2,%3}, [%4];"
                 : "=r"(r[0]), "=r"(r[1]), "=r"(r[2]), "=r"(r[3]) : "r"(addr));
}
__device__ __forceinline__ void mma16816(float* c, const uint32_t* a, const uint32_t* b) {
    asm volatile("mma.sync.aligned.m16n8k16.row.col.f32.f16.f16.f32 "
                 "{%0,%1,%2,%3}, {%4,%5,%6,%7}, {%8,%9}, {%0,%1,%2,%3};"
                 : "+f"(c[0]), "+f"(c[1]), "+f"(c[2]), "+f"(c[3])
                 : "r"(a[0]), "r"(a[1]), "r"(a[2]), "r"(a[3]), "r"(b[0]), "r"(b[1]));
}

// smem stage: exact 64B rows + SW64 swizzle. Ah(8K) Al(8K) B(8K) = 24KB/stage.
#define T_AH  0
#define T_AL  8192
#define T_B   16384
#define STAGE 24576
#define SMEMB (2 * STAGE + 128)

// ---------------- tensor-core GEMM via mma.sync fp16, A hi/lo split ----------------
// C[M,N] = act(A[M,K]fp32 @ W[K,N] + bias); W pre-rounded fp16 [N][K].
// Block tile 128x128, K-chunk 32, 256 threads (warp tile 32x64), double-buffered,
// 2 CTAs/SM. EPI: 1 = bias+relu; 2 = bias+relu -> C and C2=(1+eps)*C; 3 = bias + BN stats.
template <int EPI>
__global__ __launch_bounds__(256, 2)
void tc_gemm(const float* __restrict__ A, const __half* __restrict__ Bh,
             const float* __restrict__ bias, float* __restrict__ C, float* __restrict__ C2,
             const float* __restrict__ epsp, float* __restrict__ stats,
             int M, int N, int K)
{
    extern __shared__ __align__(16) char smraw[];
    const uint32_t sb = (smem_u32(smraw) + 127) & ~127u;

    const int tid = threadIdx.x;
    const int lane = tid & 31, wid = tid >> 5;
    const int wm = (wid & 3) * 32;       // warp M offset (4 warps)
    const int wn = (wid >> 2) * 64;      // warp N offset (2 warps)
    const int bm = blockIdx.y * 128, bn = blockIdx.x * 128;
    const int nc = K / 32;

    float acc[2][8][4];
#pragma unroll
    for (int i = 0; i < 2; i++)
#pragma unroll
        for (int j = 0; j < 8; j++)
#pragma unroll
            for (int q = 0; q < 4; q++) acc[i][j][q] = 0.f;

    // A gmem mapping: 2 threads per row, 16 floats (= 32B fp16) each
    const int arow = tid >> 1;
    const int ahalf = (tid & 1);          // which 32B half of the 64B row
    int rg = bm + arow; if (rg >= M) rg = M - 1;
    const float* aptr = A + (size_t)rg * K + ahalf * 16;
    const uint32_t abase = (uint32_t)arow * 64 + (uint32_t)ahalf * 32;
    const uint32_t asw0 = sw64(abase);        // chunk 0 (floats 0-7)
    const uint32_t asw1 = sw64(abase + 16);   // chunk 1 (floats 8-15)

    float4 ar[4];

    // ---- prologue: chunk 0 ----
#pragma unroll
    for (int j = 0; j < 4; j++) ar[j] = __ldg((const float4*)(aptr + 4 * j));
#pragma unroll
    for (int i = 0; i < 2; i++) {
        int cc = tid + 256 * i;
        int row = cc >> 2, seg = cc & 3;
        const __half* src = Bh + (size_t)(bn + row) * K + seg * 8;
        uint32_t dst = sb + T_B + sw64((uint32_t)row * 64 + seg * 16);
        asm volatile("cp.async.ca.shared.global [%0], [%1], 16;" :: "r"(dst), "l"(src));
    }
    asm volatile("cp.async.commit_group;");
    {
#pragma unroll
        for (int j = 0; j < 4; j++) {
            float4 v = ar[j];
            __half hx = __float2half(v.x), hy = __float2half(v.y);
            __half hz = __float2half(v.z), hw = __float2half(v.w);
            uint32_t h0 = pkh(hx, hy), h1 = pkh(hz, hw);
            uint32_t l0 = pkh(__float2half(v.x - __half2float(hx)),
                              __float2half(v.y - __half2float(hy)));
            uint32_t l1 = pkh(__float2half(v.z - __half2float(hz)),
                              __float2half(v.w - __half2float(hw)));
            uint32_t sw = ((j >> 1) ? asw1 : asw0) + (j & 1) * 8;
            asm volatile("st.shared.v2.b32 [%0], {%1,%2};" :: "r"(sb + T_AH + sw), "r"(h0), "r"(h1) : "memory");
            asm volatile("st.shared.v2.b32 [%0], {%1,%2};" :: "r"(sb + T_AL + sw), "r"(l0), "r"(l1) : "memory");
        }
    }
    asm volatile("cp.async.wait_group 0;");
    __syncthreads();

    // ldmatrix per-lane address components (byte offsets within tile, pre-swizzle)
    const uint32_t a_ro = (uint32_t)(lane & 15) * 64 + (uint32_t)(lane >> 4) * 16;
    const int brow = (lane & 7) + ((lane >> 4) << 3);
    const uint32_t b_ko = (uint32_t)((lane >> 3) & 1) * 16;

    for (int c = 0; c < nc; c++) {
        const uint32_t st0 = sb + (uint32_t)(c & 1) * STAGE;
        const uint32_t stn = sb + (uint32_t)((c + 1) & 1) * STAGE;
        const bool more = (c + 1 < nc);

        if (more) {
#pragma unroll
            for (int j = 0; j < 4; j++) ar[j] = __ldg((const float4*)(aptr + (c + 1) * 32 + 4 * j));
#pragma unroll
            for (int i = 0; i < 2; i++) {
                int cc = tid + 256 * i;
                int row = cc >> 2, seg = cc & 3;
                const __half* src = Bh + (size_t)(bn + row) * K + (c + 1) * 32 + seg * 8;
                uint32_t dst = stn + T_B + sw64((uint32_t)row * 64 + seg * 16);
                asm volatile("cp.async.ca.shared.global [%0], [%1], 16;" :: "r"(dst), "l"(src));
            }
            asm volatile("cp.async.commit_group;");
        }

        // ---- compute chunk c ----
#pragma unroll
        for (int ks = 0; ks < 2; ks++) {
            uint32_t ah[2][4], al[2][4], bh[4][4];
#pragma unroll
            for (int mt = 0; mt < 2; mt++) {
                uint32_t off = (uint32_t)(wm + mt * 16) * 64 + a_ro + ks * 32;
                uint32_t sw = sw64(off);
                ldm4(ah[mt], st0 + T_AH + sw);
                ldm4(al[mt], st0 + T_AL + sw);
            }
#pragma unroll
            for (int g = 0; g < 4; g++) {
                uint32_t off = (uint32_t)(wn + g * 16 + brow) * 64 + ks * 32 + b_ko;
                ldm4(bh[g], st0 + T_B + sw64(off));
            }
            // sweep 1: Ah x B
#pragma unroll
            for (int mt = 0; mt < 2; mt++)
#pragma unroll
                for (int g = 0; g < 4; g++) {
                    mma16816(acc[mt][2 * g],     ah[mt], &bh[g][0]);
                    mma16816(acc[mt][2 * g + 1], ah[mt], &bh[g][2]);
                }
            // sweep 2: Al x B
#pragma unroll
            for (int mt = 0; mt < 2; mt++)
#pragma unroll
                for (int g = 0; g < 4; g++) {
                    mma16816(acc[mt][2 * g],     al[mt], &bh[g][0]);
                    mma16816(acc[mt][2 * g + 1], al[mt], &bh[g][2]);
                }
        }

        if (more) {
#pragma unroll
            for (int j = 0; j < 4; j++) {
                float4 v = ar[j];
                __half hx = __float2half(v.x), hy = __float2half(v.y);
                __half hz = __float2half(v.z), hw = __float2half(v.w);
                uint32_t h0 = pkh(hx, hy), h1 = pkh(hz, hw);
                uint32_t l0 = pkh(__float2half(v.x - __half2float(hx)),
                                  __float2half(v.y - __half2float(hy)));
                uint32_t l1 = pkh(__float2half(v.z - __half2float(hz)),
                                  __float2half(v.w - __half2float(hw)));
                uint32_t sw = ((j >> 1) ? asw1 : asw0) + (j & 1) * 8;
                asm volatile("st.shared.v2.b32 [%0], {%1,%2};" :: "r"(stn + T_AH + sw), "r"(h0), "r"(h1) : "memory");
                asm volatile("st.shared.v2.b32 [%0], {%1,%2};" :: "r"(stn + T_AL + sw), "r"(l0), "r"(l1) : "memory");
            }
        }
        asm volatile("cp.async.wait_group 0;");
        __syncthreads();
    }

    // ---- epilogue ----
    float* ssum = reinterpret_cast<float*>(smraw);        // [128]
    float* ssq  = reinterpret_cast<float*>(smraw) + 128;  // [128]
    if (EPI == 3) {
        if (tid < 256) reinterpret_cast<float*>(smraw)[tid] = 0.f;
        __syncthreads();
    }

    float emul = 0.f;
    if (EPI == 2) emul = 1.0f + __ldg(epsp);
#pragma unroll
    for (int mt = 0; mt < 2; mt++) {
        int r0 = bm + wm + mt * 16 + (lane >> 2);
        int r1 = r0 + 8;
#pragma unroll
        for (int nt = 0; nt < 8; nt++) {
            int col = bn + wn + nt * 8 + (lane & 3) * 2;
            float2 bv = *reinterpret_cast<const float2*>(&bias[col]);
            float v0 = acc[mt][nt][0] + bv.x;
            float v1 = acc[mt][nt][1] + bv.y;
            float v2 = acc[mt][nt][2] + bv.x;
            float v3 = acc[mt][nt][3] + bv.y;
            if (EPI == 1 || EPI == 2) {
                v0 = fmaxf(v0, 0.f); v1 = fmaxf(v1, 0.f);
                v2 = fmaxf(v2, 0.f); v3 = fmaxf(v3, 0.f);
            }
            bool k0 = r0 < M, k1 = r1 < M;
            if (k0) {
                *reinterpret_cast<float2*>(&C[(size_t)r0 * N + col]) = make_float2(v0, v1);
                if (EPI == 2)
                    *reinterpret_cast<float2*>(&C2[(size_t)r0 * N + col]) = make_float2(emul * v0, emul * v1);
            }
            if (k1) {
                *reinterpret_cast<float2*>(&C[(size_t)r1 * N + col]) = make_float2(v2, v3);
                if (EPI == 2)
                    *reinterpret_cast<float2*>(&C2[(size_t)r1 * N + col]) = make_float2(emul * v2, emul * v3);
            }
            if (EPI == 3) {
                float a0 = (k0 ? v0 : 0.f) + (k1 ? v2 : 0.f);
                float a1 = (k0 ? v1 : 0.f) + (k1 ? v3 : 0.f);
                float q0 = (k0 ? v0 * v0 : 0.f) + (k1 ? v2 * v2 : 0.f);
                float q1 = (k0 ? v1 * v1 : 0.f) + (k1 ? v3 * v3 : 0.f);
                // reduce across lanes sharing the same column (lane & 3 groups)
#pragma unroll
                for (int off = 16; off >= 4; off >>= 1) {
                    a0 += __shfl_xor_sync(0xffffffffu, a0, off);
                    a1 += __shfl_xor_sync(0xffffffffu, a1, off);
                    q0 += __shfl_xor_sync(0xffffffffu, q0, off);
                    q1 += __shfl_xor_sync(0xffffffffu, q1, off);
                }
                if (lane < 4) {
                    int lc = wn + nt * 8 + lane * 2;
                    atomicAdd(&ssum[lc], a0);
                    atomicAdd(&ssum[lc + 1], a1);
                    atomicAdd(&ssq[lc], q0);
                    atomicAdd(&ssq[lc + 1], q1);
                }
            }
        }
    }
    if (EPI == 3) {
        __syncthreads();
        if (tid < 128) {
            atomicAdd(&stats[bn + tid], ssum[tid]);
            atomicAdd(&stats[HDIM + bn + tid], ssq[tid]);
        }
    }
}

// ---------------- all-weight conversion: transpose + fp16 round (one launch) ----------------
#define NW_IN (128 * 256)
#define NW_1  (256 * 512)
#define NW_2  (512 * 256)
__global__ void conv_w_all(const float* __restrict__ W_in, const float* __restrict__ W1,
                           const float* __restrict__ W2, __half* __restrict__ wh)
{
    int idx = blockIdx.x * blockDim.x + threadIdx.x;
    if (idx < NW_IN) {
        int n = idx / 128, k = idx % 128;
        wh[WIN_OFF + idx] = __float2half(W_in[(size_t)k * 256 + n]);
    } else if (idx < NW_IN + NLAYER * NW_1) {
        int t = idx - NW_IN;
        int l = t / NW_1, r = t % NW_1;
        int n = r / 256, k = r % 256;
        wh[W1_OFF + t] = __float2half(W1[(size_t)l * NW_1 + (size_t)k * 512 + n]);
    } else if (idx < NW_IN + NLAYER * (NW_1 + NW_2)) {
        int t = idx - NW_IN - NLAYER * NW_1;
        int l = t / NW_2, r = t % NW_2;
        int n = r / 512, k = r % 512;
        wh[W2_OFF + t] = __float2half(W2[(size_t)l * NW_2 + (size_t)k * 256 + n]);
    }
}

// ---------------- edge scatter: agg[dst] += h[src] ----------------
__global__ void scatter_kernel(const float* __restrict__ h, const int* __restrict__ src,
                               const int* __restrict__ dst, float* __restrict__ agg, int E)
{
    int idx = blockIdx.x * blockDim.x + threadIdx.x;
    int e = idx >> 6;
    if (e >= E) return;
    int c4 = (idx & 63) << 2;
    int s = __ldg(&src[e]);
    int d = __ldg(&dst[e]);
    float4 v = __ldg(reinterpret_cast<const float4*>(&h[(size_t)s * HDIM + c4]));
    float* o = &agg[(size_t)d * HDIM + c4];
    atomicAdd(o + 0, v.x);
    atomicAdd(o + 1, v.y);
    atomicAdd(o + 2, v.z);
    atomicAdd(o + 3, v.w);
}

// ---------------- BN apply + relu ----------------
// POOL=0: write h and agg=(1+eps_next)*h. POOL=1: atomic-add into per-graph pool only.
template <int POOL>
__global__ void bn_apply_kernel(const float4* __restrict__ z, const float* __restrict__ stats,
                                const float* __restrict__ gamma, const float* __restrict__ beta,
                                const float* __restrict__ epsn,
                                float4* __restrict__ h, float4* __restrict__ agg,
                                const int* __restrict__ batch, float* __restrict__ pool,
                                int total4)
{
    int i = blockIdx.x * blockDim.x + threadIdx.x;
    if (i >= total4) return;
    int c = (i << 2) & (HDIM - 1);
    const float invN = 1.0f / (float)NNODES;
    float4 s = *reinterpret_cast<const float4*>(&stats[c]);
    float4 q = *reinterpret_cast<const float4*>(&stats[HDIM + c]);
    float4 g = *reinterpret_cast<const float4*>(&gamma[c]);
    float4 b = *reinterpret_cast<const float4*>(&beta[c]);
    float4 zv = z[i];
    float4 r;
    {
        float mu = s.x * invN, var = q.x * invN - mu * mu;
        r.x = fmaxf((zv.x - mu) * (g.x * rsqrtf(var + BN_EPS)) + b.x, 0.f);
    }
    {
        float mu = s.y * invN, var = q.y * invN - mu * mu;
        r.y = fmaxf((zv.y - mu) * (g.y * rsqrtf(var + BN_EPS)) + b.y, 0.f);
    }
    {
        float mu = s.z * invN, var = q.z * invN - mu * mu;
        r.z = fmaxf((zv.z - mu) * (g.z * rsqrtf(var + BN_EPS)) + b.z, 0.f);
    }
    {
        float mu = s.w * invN, var = q.w * invN - mu * mu;
        r.w = fmaxf((zv.w - mu) * (g.w * rsqrtf(var + BN_EPS)) + b.w, 0.f);
    }
    if (POOL == 0) {
        h[i] = r;
        float e = 1.0f + __ldg(epsn);
        float4 a; a.x = e * r.x; a.y = e * r.y; a.z = e * r.z; a.w = e * r.w;
        agg[i] = a;
    } else {
        int node = i >> 6;
        int gidx = __ldg(&batch[node]);
        float* o = &pool[(size_t)gidx * HDIM + c];
        atomicAdd(o + 0, r.x);
        atomicAdd(o + 1, r.y);
        atomicAdd(o + 2, r.z);
        atomicAdd(o + 3, r.w);
    }
}

// ---------------- per-graph node counts ----------------
__global__ void count_kernel(const int* __restrict__ batch, float* __restrict__ cnt, int n)
{
    int i = blockIdx.x * blockDim.x + threadIdx.x;
    if (i < n) atomicAdd(&cnt[__ldg(&batch[i])], 1.0f);
}

// ---------------- predictor head ----------------
__global__ void head_kernel(const float* __restrict__ pooled, const float* __restrict__ cnt,
                            const float* __restrict__ Wp1, const float* __restrict__ bp1,
                            const float* __restrict__ Wp2, const float* __restrict__ bp2,
                            float* __restrict__ out)
{
    __shared__ float sp[HDIM];
    __shared__ float red[128];
    int g = blockIdx.x;
    int tid = threadIdx.x;   // 128 threads
    float inv = 1.0f / fmaxf(__ldg(&cnt[g]), 1.0f);
    for (int k = tid; k < HDIM; k += 128)
        sp[k] = pooled[(size_t)g * HDIM + k] * inv;
    __syncthreads();

    float s = __ldg(&bp1[tid]);
#pragma unroll 4
    for (int k = 0; k < HDIM; k++)
        s = fmaf(sp[k], __ldg(&Wp1[k * 128 + tid]), s);
    s = fmaxf(s, 0.f);
    float t = s * __ldg(&Wp2[tid]);

    red[tid] = t;
    __syncthreads();
    for (int off = 64; off > 0; off >>= 1) {
        if (tid < off) red[tid] += red[tid + off];
        __syncthreads();
    }
    if (tid == 0) out[g] = red[0] + __ldg(&bp2[0]);
}

// ---------------- host launch ----------------
static void* sym_addr(const void* symbol)
{
    void* p = nullptr;
    cudaGetSymbolAddress(&p, symbol);
    return p;
}

extern "C" void kernel_launch(void* const* d_in, const int* in_sizes, int n_in,
                              void* d_out, int out_size)
{
    const float* x      = (const float*)d_in[0];
    const int*   ei     = (const int*)d_in[1];
    const int*   batch  = (const int*)d_in[2];
    const float* W_in   = (const float*)d_in[3];
    const float* b_in   = (const float*)d_in[4];
    const float* eps    = (const float*)d_in[5];
    const float* W1     = (const float*)d_in[6];
    const float* b1     = (const float*)d_in[7];
    const float* W2     = (const float*)d_in[8];
    const float* b2     = (const float*)d_in[9];
    const float* gamma  = (const float*)d_in[10];
    const float* beta   = (const float*)d_in[11];
    const float* Wp1    = (const float*)d_in[12];
    const float* bp1    = (const float*)d_in[13];
    const float* Wp2    = (const float*)d_in[14];
    const float* bp2    = (const float*)d_in[15];
    float* out = (float*)d_out;

    const int E = in_sizes[1] / 2;
    const int* src = ei;
    const int* dst = ei + E;

    float* h     = (float*)sym_addr(g_h);
    float* agg   = (float*)sym_addr(g_agg);
    float* z1    = (float*)sym_addr(g_z1);
    float* z2    = (float*)sym_addr(g_z2);
    float* stats = (float*)sym_addr(g_stats);
    float* pool  = (float*)sym_addr(g_pool);
    float* cnt   = (float*)sym_addr(g_cnt);
    __half* wh   = (__half*)sym_addr(g_wh);

    cudaFuncSetAttribute(tc_gemm<1>, cudaFuncAttributeMaxDynamicSharedMemorySize, SMEMB);
    cudaFuncSetAttribute(tc_gemm<2>, cudaFuncAttributeMaxDynamicSharedMemorySize, SMEMB);
    cudaFuncSetAttribute(tc_gemm<3>, cudaFuncAttributeMaxDynamicSharedMemorySize, SMEMB);

    const int M = NNODES;
    const int mt = (M + 127) / 128;    // 782
    const int totalH = M * HDIM;
    const int total4 = totalH / 4;

    // ---- weight prep (single launch) ----
    {
        int tot = NW_IN + NLAYER * (NW_1 + NW_2);
        conv_w_all<<<(tot + 255) / 256, 256>>>(W_in, W1, W2, wh);
    }

    // ---- input projection: h = relu(x@W_in + b_in), agg = (1+eps0)*h ----
    tc_gemm<2><<<dim3(2, mt), 256, SMEMB>>>(x, wh + WIN_OFF, b_in, h, agg, eps, nullptr,
                                            M, HDIM, DIN);

    for (int l = 0; l < NLAYER; l++) {
        // agg[dst] += h[src]
        {
            long long tot = (long long)E * 64;
            scatter_kernel<<<(int)((tot + 255) / 256), 256>>>(h, src, dst, agg, E);
        }
        // z1 = relu(agg @ W1_l + b1_l)
        tc_gemm<1><<<dim3(4, mt), 256, SMEMB>>>(agg, wh + W1_OFF + (size_t)l * H2 * HDIM,
                                                b1 + (size_t)l * H2, z1, nullptr, nullptr,
                                                nullptr, M, H2, HDIM);
        // z2 = z1 @ W2_l + b2_l (+ fused BN stats)
        cudaMemsetAsync(stats, 0, 2 * HDIM * sizeof(float));
        tc_gemm<3><<<dim3(2, mt), 256, SMEMB>>>(z1, wh + W2_OFF + (size_t)l * HDIM * H2,
                                                b2 + (size_t)l * HDIM, z2, nullptr, nullptr,
                                                stats, M, HDIM, H2);
        // BN apply + relu
        if (l + 1 < NLAYER) {
            bn_apply_kernel<0><<<(total4 + 255) / 256, 256>>>(
                (const float4*)z2, stats, gamma + (size_t)l * HDIM, beta + (size_t)l * HDIM,
                eps + (l + 1), (float4*)h, (float4*)agg, nullptr, nullptr, total4);
        } else {
            cudaMemsetAsync(pool, 0, NGRAPH * HDIM * sizeof(float));
            cudaMemsetAsync(cnt, 0, NGRAPH * sizeof(float));
            count_kernel<<<(M + 255) / 256, 256>>>(batch, cnt, M);
            bn_apply_kernel<1><<<(total4 + 255) / 256, 256>>>(
                (const float4*)z2, stats, gamma + (size_t)l * HDIM, beta + (size_t)l * HDIM,
                nullptr, nullptr, nullptr, batch, pool, total4);
        }
    }

    // ---- head ----
    head_kernel<<<NGRAPH, 128>>>(pool, cnt, Wp1, bp1, Wp2, bp2, out);
}

// round 6
// speedup vs baseline: 1.8948x; 1.2068x over previous
#include <cuda_runtime.h>
#include <cuda_fp16.h>
#include <cstdint>

// ---------------- constants (problem-fixed) ----------------
#define NNODES 100000
#define DIN    128
#define HDIM   256
#define H2     512
#define NLAYER 4
#define NGRAPH 512
#define BN_EPS 1e-5f

// ---------------- scratch (device globals; no allocation allowed) ----------------
__device__ __half g_h16[NNODES * HDIM];   // node features, fp16 (scatter input)
__device__ float g_agg[NNODES * HDIM];    // (1+eps)h + scatter (fp32 atomics)
__device__ __half g_z1[NNODES * H2];      // MLP hidden, fp16
__device__ float g_z2[NNODES * HDIM];     // MLP out (pre-BN)
__device__ float g_stats[2 * HDIM];       // [sums | sumsq]
__device__ float g_pool[NGRAPH * HDIM];   // per-graph sums
__device__ float g_cnt[NGRAPH];           // per-graph counts

// converted weights: transposed [N][K], fp16
#define WIN_OFF  0
#define W1_OFF   (256 * 128)
#define W2_OFF   (W1_OFF + NLAYER * 512 * 256)
#define WT_TOTAL (W2_OFF + NLAYER * 256 * 512)
__device__ __align__(16) __half g_wh[WT_TOTAL];

// ---------------- helpers ----------------
__device__ __forceinline__ uint32_t smem_u32(const void* p) {
    uint32_t a;
    asm("{ .reg .u64 t; cvta.to.shared.u64 t, %1; cvt.u32.u64 %0, t; }" : "=r"(a) : "l"(p));
    return a;
}
__device__ __forceinline__ uint32_t pkh(float a, float b) {
    __half2 t; t.x = __float2half(a); t.y = __float2half(b);
    return *reinterpret_cast<uint32_t*>(&t);
}
__device__ __forceinline__ uint32_t sw64(uint32_t off) {
    return off ^ ((off >> 3) & 0x30);
}
__device__ __forceinline__ void ldm4(uint32_t* r, uint32_t addr) {
    asm volatile("ldmatrix.sync.aligned.m8n8.x4.shared.b16 {%0,%1,%2,%3}, [%4];"
                 : "=r"(r[0]), "=r"(r[1]), "=r"(r[2]), "=r"(r[3]) : "r"(addr));
}
__device__ __forceinline__ void mma16816(float* c, const uint32_t* a, const uint32_t* b) {
    asm volatile("mma.sync.aligned.m16n8k16.row.col.f32.f16.f16.f32 "
                 "{%0,%1,%2,%3}, {%4,%5,%6,%7}, {%8,%9}, {%0,%1,%2,%3};"
                 : "+f"(c[0]), "+f"(c[1]), "+f"(c[2]), "+f"(c[3])
                 : "r"(a[0]), "r"(a[1]), "r"(a[2]), "r"(a[3]), "r"(b[0]), "r"(b[1]));
}

// smem stage: exact 64B rows + SW64 swizzle. A(8K) B(8K) = 16KB/stage.
#define T_A   0
#define T_B   8192
#define STAGE 16384
#define SMEMB (2 * STAGE + 128)

// ---------------- tensor-core GEMM via mma.sync fp16 ----------------
// C[M,N] = act(A[M,K] @ W[K,N] + bias); W fp16 [N][K].
// Block tile 128x128, K-chunk 32, 256 threads (warp tile 32x64), double-buffered,
// 2 CTAs/SM.
// AFP16: 0 = A fp32 (convert in-flight), 1 = A fp16 (cp.async).
// EPI: 1 = bias+relu -> fp16 C; 2 = bias+relu -> fp16 C and fp32 C2=(1+eps)*v;
//      3 = bias -> fp32 C + fused BN stats.
template <int EPI, int AFP16>
__global__ __launch_bounds__(256, 2)
void tc_gemm(const void* __restrict__ Ap, const __half* __restrict__ Bh,
             const float* __restrict__ bias, void* __restrict__ Cp, float* __restrict__ C2,
             const float* __restrict__ epsp, float* __restrict__ stats,
             int M, int N, int K)
{
    extern __shared__ __align__(16) char smraw[];
    const uint32_t sb = (smem_u32(smraw) + 127) & ~127u;

    const int tid = threadIdx.x;
    const int lane = tid & 31, wid = tid >> 5;
    const int wm = (wid & 3) * 32;       // warp M offset (4 warps)
    const int wn = (wid >> 2) * 64;      // warp N offset (2 warps)
    const int bm = blockIdx.y * 128, bn = blockIdx.x * 128;
    const int nc = K / 32;

    float acc[2][8][4];
#pragma unroll
    for (int i = 0; i < 2; i++)
#pragma unroll
        for (int j = 0; j < 8; j++)
#pragma unroll
            for (int q = 0; q < 4; q++) acc[i][j][q] = 0.f;

    // ---- A load setup ----
    const float* af = (const float*)Ap;
    const __half* ah16 = (const __half*)Ap;
    // fp32 path: 2 threads per row, 16 floats each
    const int arow = tid >> 1;
    const int ahalf = tid & 1;
    int rga = bm + arow; if (rga >= M) rga = M - 1;
    const float* aptr = af + (size_t)rga * K + ahalf * 16;
    const uint32_t abase = (uint32_t)arow * 64 + (uint32_t)ahalf * 32;
    const uint32_t asw0 = sw64(abase);
    const uint32_t asw1 = sw64(abase + 16);
    // fp16 path: 512 x 16B segments, 2 per thread
    int arow0 = (tid * 2) >> 2, aseg0 = (tid * 2) & 3;
    int arow1 = (tid * 2 + 1) >> 2, aseg1 = (tid * 2 + 1) & 3;
    int rg0 = bm + arow0; if (rg0 >= M) rg0 = M - 1;
    int rg1 = bm + arow1; if (rg1 >= M) rg1 = M - 1;
    const uint32_t adst0 = sw64((uint32_t)arow0 * 64 + aseg0 * 16);
    const uint32_t adst1 = sw64((uint32_t)arow1 * 64 + aseg1 * 16);

    float4 ar[4];

#define LOAD_A_CHUNK(cc, stg)                                                            \
    do {                                                                                 \
        if (AFP16) {                                                                     \
            const __half* s0 = ah16 + (size_t)rg0 * K + (cc) * 32 + aseg0 * 8;           \
            const __half* s1 = ah16 + (size_t)rg1 * K + (cc) * 32 + aseg1 * 8;           \
            asm volatile("cp.async.ca.shared.global [%0], [%1], 16;" :: "r"((stg) + T_A + adst0), "l"(s0)); \
            asm volatile("cp.async.ca.shared.global [%0], [%1], 16;" :: "r"((stg) + T_A + adst1), "l"(s1)); \
        }                                                                                \
    } while (0)

#define CONV_A_CHUNK(stg)                                                                \
    do {                                                                                 \
        if (!AFP16) {                                                                    \
            _Pragma("unroll")                                                            \
            for (int j = 0; j < 4; j++) {                                                \
                float4 v = ar[j];                                                        \
                uint32_t h0 = pkh(v.x, v.y), h1 = pkh(v.z, v.w);                         \
                uint32_t sw = ((j >> 1) ? asw1 : asw0) + (j & 1) * 8;                    \
                asm volatile("st.shared.v2.b32 [%0], {%1,%2};" :: "r"((stg) + T_A + sw), "r"(h0), "r"(h1) : "memory"); \
            }                                                                            \
        }                                                                                \
    } while (0)

    // ---- prologue: chunk 0 ----
    if (!AFP16) {
#pragma unroll
        for (int j = 0; j < 4; j++) ar[j] = __ldg((const float4*)(aptr + 4 * j));
    }
    LOAD_A_CHUNK(0, sb);
#pragma unroll
    for (int i = 0; i < 2; i++) {
        int cc = tid + 256 * i;
        int row = cc >> 2, seg = cc & 3;
        const __half* src = Bh + (size_t)(bn + row) * K + seg * 8;
        uint32_t dst = sb + T_B + sw64((uint32_t)row * 64 + seg * 16);
        asm volatile("cp.async.ca.shared.global [%0], [%1], 16;" :: "r"(dst), "l"(src));
    }
    asm volatile("cp.async.commit_group;");
    CONV_A_CHUNK(sb);
    asm volatile("cp.async.wait_group 0;");
    __syncthreads();

    // ldmatrix per-lane address components
    const uint32_t a_ro = (uint32_t)(lane & 15) * 64 + (uint32_t)(lane >> 4) * 16;
    const int brow = (lane & 7) + ((lane >> 4) << 3);
    const uint32_t b_ko = (uint32_t)((lane >> 3) & 1) * 16;

    for (int c = 0; c < nc; c++) {
        const uint32_t st0 = sb + (uint32_t)(c & 1) * STAGE;
        const uint32_t stn = sb + (uint32_t)((c + 1) & 1) * STAGE;
        const bool more = (c + 1 < nc);

        if (more) {
            if (!AFP16) {
#pragma unroll
                for (int j = 0; j < 4; j++) ar[j] = __ldg((const float4*)(aptr + (c + 1) * 32 + 4 * j));
            }
            LOAD_A_CHUNK(c + 1, stn);
#pragma unroll
            for (int i = 0; i < 2; i++) {
                int cc = tid + 256 * i;
                int row = cc >> 2, seg = cc & 3;
                const __half* src = Bh + (size_t)(bn + row) * K + (c + 1) * 32 + seg * 8;
                uint32_t dst = stn + T_B + sw64((uint32_t)row * 64 + seg * 16);
                asm volatile("cp.async.ca.shared.global [%0], [%1], 16;" :: "r"(dst), "l"(src));
            }
            asm volatile("cp.async.commit_group;");
        }

        // ---- compute chunk c ----
#pragma unroll
        for (int ks = 0; ks < 2; ks++) {
            uint32_t ah[2][4], bh[4][4];
#pragma unroll
            for (int mt = 0; mt < 2; mt++) {
                uint32_t off = (uint32_t)(wm + mt * 16) * 64 + a_ro + ks * 32;
                ldm4(ah[mt], st0 + T_A + sw64(off));
            }
#pragma unroll
            for (int g = 0; g < 4; g++) {
                uint32_t off = (uint32_t)(wn + g * 16 + brow) * 64 + ks * 32 + b_ko;
                ldm4(bh[g], st0 + T_B + sw64(off));
            }
#pragma unroll
            for (int mt = 0; mt < 2; mt++)
#pragma unroll
                for (int g = 0; g < 4; g++) {
                    mma16816(acc[mt][2 * g],     ah[mt], &bh[g][0]);
                    mma16816(acc[mt][2 * g + 1], ah[mt], &bh[g][2]);
                }
        }

        if (more) CONV_A_CHUNK(stn);
        asm volatile("cp.async.wait_group 0;");
        __syncthreads();
    }

    // ---- epilogue ----
    float* ssum = reinterpret_cast<float*>(smraw);        // [128]
    float* ssq  = reinterpret_cast<float*>(smraw) + 128;  // [128]
    if (EPI == 3) {
        if (tid < 256) reinterpret_cast<float*>(smraw)[tid] = 0.f;
        __syncthreads();
    }

    __half* Ch = (__half*)Cp;
    float*  Cf = (float*)Cp;
    float emul = 0.f;
    if (EPI == 2) emul = 1.0f + __ldg(epsp);
#pragma unroll
    for (int mt = 0; mt < 2; mt++) {
        int r0 = bm + wm + mt * 16 + (lane >> 2);
        int r1 = r0 + 8;
#pragma unroll
        for (int nt = 0; nt < 8; nt++) {
            int col = bn + wn + nt * 8 + (lane & 3) * 2;
            float2 bv = *reinterpret_cast<const float2*>(&bias[col]);
            float v0 = acc[mt][nt][0] + bv.x;
            float v1 = acc[mt][nt][1] + bv.y;
            float v2 = acc[mt][nt][2] + bv.x;
            float v3 = acc[mt][nt][3] + bv.y;
            if (EPI == 1 || EPI == 2) {
                v0 = fmaxf(v0, 0.f); v1 = fmaxf(v1, 0.f);
                v2 = fmaxf(v2, 0.f); v3 = fmaxf(v3, 0.f);
            }
            bool k0 = r0 < M, k1 = r1 < M;
            if (EPI == 1 || EPI == 2) {
                if (k0) *reinterpret_cast<uint32_t*>(&Ch[(size_t)r0 * N + col]) = pkh(v0, v1);
                if (k1) *reinterpret_cast<uint32_t*>(&Ch[(size_t)r1 * N + col]) = pkh(v2, v3);
                if (EPI == 2) {
                    if (k0) *reinterpret_cast<float2*>(&C2[(size_t)r0 * N + col]) = make_float2(emul * v0, emul * v1);
                    if (k1) *reinterpret_cast<float2*>(&C2[(size_t)r1 * N + col]) = make_float2(emul * v2, emul * v3);
                }
            } else {
                if (k0) *reinterpret_cast<float2*>(&Cf[(size_t)r0 * N + col]) = make_float2(v0, v1);
                if (k1) *reinterpret_cast<float2*>(&Cf[(size_t)r1 * N + col]) = make_float2(v2, v3);
                float a0 = (k0 ? v0 : 0.f) + (k1 ? v2 : 0.f);
                float a1 = (k0 ? v1 : 0.f) + (k1 ? v3 : 0.f);
                float q0 = (k0 ? v0 * v0 : 0.f) + (k1 ? v2 * v2 : 0.f);
                float q1 = (k0 ? v1 * v1 : 0.f) + (k1 ? v3 * v3 : 0.f);
#pragma unroll
                for (int off = 16; off >= 4; off >>= 1) {
                    a0 += __shfl_xor_sync(0xffffffffu, a0, off);
                    a1 += __shfl_xor_sync(0xffffffffu, a1, off);
                    q0 += __shfl_xor_sync(0xffffffffu, q0, off);
                    q1 += __shfl_xor_sync(0xffffffffu, q1, off);
                }
                if (lane < 4) {
                    int lc = wn + nt * 8 + lane * 2;
                    atomicAdd(&ssum[lc], a0);
                    atomicAdd(&ssum[lc + 1], a1);
                    atomicAdd(&ssq[lc], q0);
                    atomicAdd(&ssq[lc + 1], q1);
                }
            }
        }
    }
    if (EPI == 3) {
        __syncthreads();
        if (tid < 128) {
            atomicAdd(&stats[bn + tid], ssum[tid]);
            atomicAdd(&stats[HDIM + bn + tid], ssq[tid]);
        }
    }
}

// ---------------- all-weight conversion: transpose + fp16 round (one launch) ----------------
#define NW_IN (128 * 256)
#define NW_1  (256 * 512)
#define NW_2  (512 * 256)
__global__ void conv_w_all(const float* __restrict__ W_in, const float* __restrict__ W1,
                           const float* __restrict__ W2, __half* __restrict__ wh)
{
    int idx = blockIdx.x * blockDim.x + threadIdx.x;
    if (idx < NW_IN) {
        int n = idx / 128, k = idx % 128;
        wh[WIN_OFF + idx] = __float2half(W_in[(size_t)k * 256 + n]);
    } else if (idx < NW_IN + NLAYER * NW_1) {
        int t = idx - NW_IN;
        int l = t / NW_1, r = t % NW_1;
        int n = r / 256, k = r % 256;
        wh[W1_OFF + t] = __float2half(W1[(size_t)l * NW_1 + (size_t)k * 512 + n]);
    } else if (idx < NW_IN + NLAYER * (NW_1 + NW_2)) {
        int t = idx - NW_IN - NLAYER * NW_1;
        int l = t / NW_2, r = t % NW_2;
        int n = r / 512, k = r % 512;
        wh[W2_OFF + t] = __float2half(W2[(size_t)l * NW_2 + (size_t)k * 256 + n]);
    }
}

// ---------------- edge scatter: agg[dst] += h16[src] (fp16 read, fp32 atomics) ----------------
__global__ void scatter_kernel(const __half* __restrict__ h, const int* __restrict__ src,
                               const int* __restrict__ dst, float* __restrict__ agg, int E)
{
    int idx = blockIdx.x * blockDim.x + threadIdx.x;
    int e = idx >> 6;
    if (e >= E) return;
    int c4 = (idx & 63) << 2;
    int s = __ldg(&src[e]);
    int d = __ldg(&dst[e]);
    __half2 p01, p23;
    {
        uint2 u = __ldg(reinterpret_cast<const uint2*>(&h[(size_t)s * HDIM + c4]));
        p01 = *reinterpret_cast<__half2*>(&u.x);
        p23 = *reinterpret_cast<__half2*>(&u.y);
    }
    float* o = &agg[(size_t)d * HDIM + c4];
    atomicAdd(o + 0, __half2float(p01.x));
    atomicAdd(o + 1, __half2float(p01.y));
    atomicAdd(o + 2, __half2float(p23.x));
    atomicAdd(o + 3, __half2float(p23.y));
}

// ---------------- BN apply + relu ----------------
// POOL=0: write h16 (fp16) and agg=(1+eps_next)*h (fp32). POOL=1: per-graph pool atomics.
template <int POOL>
__global__ void bn_apply_kernel(const float4* __restrict__ z, const float* __restrict__ stats,
                                const float* __restrict__ gamma, const float* __restrict__ beta,
                                const float* __restrict__ epsn,
                                uint2* __restrict__ h16, float4* __restrict__ agg,
                                const int* __restrict__ batch, float* __restrict__ pool,
                                int total4)
{
    int i = blockIdx.x * blockDim.x + threadIdx.x;
    if (i >= total4) return;
    int c = (i << 2) & (HDIM - 1);
    const float invN = 1.0f / (float)NNODES;
    float4 s = *reinterpret_cast<const float4*>(&stats[c]);
    float4 q = *reinterpret_cast<const float4*>(&stats[HDIM + c]);
    float4 g = *reinterpret_cast<const float4*>(&gamma[c]);
    float4 b = *reinterpret_cast<const float4*>(&beta[c]);
    float4 zv = z[i];
    float4 r;
    {
        float mu = s.x * invN, var = q.x * invN - mu * mu;
        r.x = fmaxf((zv.x - mu) * (g.x * rsqrtf(var + BN_EPS)) + b.x, 0.f);
    }
    {
        float mu = s.y * invN, var = q.y * invN - mu * mu;
        r.y = fmaxf((zv.y - mu) * (g.y * rsqrtf(var + BN_EPS)) + b.y, 0.f);
    }
    {
        float mu = s.z * invN, var = q.z * invN - mu * mu;
        r.z = fmaxf((zv.z - mu) * (g.z * rsqrtf(var + BN_EPS)) + b.z, 0.f);
    }
    {
        float mu = s.w * invN, var = q.w * invN - mu * mu;
        r.w = fmaxf((zv.w - mu) * (g.w * rsqrtf(var + BN_EPS)) + b.w, 0.f);
    }
    if (POOL == 0) {
        uint2 p;
        __half2 a01; a01.x = __float2half(r.x); a01.y = __float2half(r.y);
        __half2 a23; a23.x = __float2half(r.z); a23.y = __float2half(r.w);
        p.x = *reinterpret_cast<uint32_t*>(&a01);
        p.y = *reinterpret_cast<uint32_t*>(&a23);
        h16[i] = p;
        float e = 1.0f + __ldg(epsn);
        float4 a; a.x = e * r.x; a.y = e * r.y; a.z = e * r.z; a.w = e * r.w;
        agg[i] = a;
    } else {
        int node = i >> 6;
        int gidx = __ldg(&batch[node]);
        float* o = &pool[(size_t)gidx * HDIM + c];
        atomicAdd(o + 0, r.x);
        atomicAdd(o + 1, r.y);
        atomicAdd(o + 2, r.z);
        atomicAdd(o + 3, r.w);
    }
}

// ---------------- per-graph node counts ----------------
__global__ void count_kernel(const int* __restrict__ batch, float* __restrict__ cnt, int n)
{
    int i = blockIdx.x * blockDim.x + threadIdx.x;
    if (i < n) atomicAdd(&cnt[__ldg(&batch[i])], 1.0f);
}

// ---------------- predictor head ----------------
__global__ void head_kernel(const float* __restrict__ pooled, const float* __restrict__ cnt,
                            const float* __restrict__ Wp1, const float* __restrict__ bp1,
                            const float* __restrict__ Wp2, const float* __restrict__ bp2,
                            float* __restrict__ out)
{
    __shared__ float sp[HDIM];
    __shared__ float red[128];
    int g = blockIdx.x;
    int tid = threadIdx.x;   // 128 threads
    float inv = 1.0f / fmaxf(__ldg(&cnt[g]), 1.0f);
    for (int k = tid; k < HDIM; k += 128)
        sp[k] = pooled[(size_t)g * HDIM + k] * inv;
    __syncthreads();

    float s = __ldg(&bp1[tid]);
#pragma unroll 4
    for (int k = 0; k < HDIM; k++)
        s = fmaf(sp[k], __ldg(&Wp1[k * 128 + tid]), s);
    s = fmaxf(s, 0.f);
    float t = s * __ldg(&Wp2[tid]);

    red[tid] = t;
    __syncthreads();
    for (int off = 64; off > 0; off >>= 1) {
        if (tid < off) red[tid] += red[tid + off];
        __syncthreads();
    }
    if (tid == 0) out[g] = red[0] + __ldg(&bp2[0]);
}

// ---------------- host launch ----------------
static void* sym_addr(const void* symbol)
{
    void* p = nullptr;
    cudaGetSymbolAddress(&p, symbol);
    return p;
}

extern "C" void kernel_launch(void* const* d_in, const int* in_sizes, int n_in,
                              void* d_out, int out_size)
{
    const float* x      = (const float*)d_in[0];
    const int*   ei     = (const int*)d_in[1];
    const int*   batch  = (const int*)d_in[2];
    const float* W_in   = (const float*)d_in[3];
    const float* b_in   = (const float*)d_in[4];
    const float* eps    = (const float*)d_in[5];
    const float* W1     = (const float*)d_in[6];
    const float* b1     = (const float*)d_in[7];
    const float* W2     = (const float*)d_in[8];
    const float* b2     = (const float*)d_in[9];
    const float* gamma  = (const float*)d_in[10];
    const float* beta   = (const float*)d_in[11];
    const float* Wp1    = (const float*)d_in[12];
    const float* bp1    = (const float*)d_in[13];
    const float* Wp2    = (const float*)d_in[14];
    const float* bp2    = (const float*)d_in[15];
    float* out = (float*)d_out;

    const int E = in_sizes[1] / 2;
    const int* src = ei;
    const int* dst = ei + E;

    __half* h16  = (__half*)sym_addr(g_h16);
    float* agg   = (float*)sym_addr(g_agg);
    __half* z1   = (__half*)sym_addr(g_z1);
    float* z2    = (float*)sym_addr(g_z2);
    float* stats = (float*)sym_addr(g_stats);
    float* pool  = (float*)sym_addr(g_pool);
    float* cnt   = (float*)sym_addr(g_cnt);
    __half* wh   = (__half*)sym_addr(g_wh);

    cudaFuncSetAttribute((const void*)tc_gemm<1, 0>, cudaFuncAttributeMaxDynamicSharedMemorySize, SMEMB);
    cudaFuncSetAttribute((const void*)tc_gemm<2, 0>, cudaFuncAttributeMaxDynamicSharedMemorySize, SMEMB);
    cudaFuncSetAttribute((const void*)tc_gemm<3, 1>, cudaFuncAttributeMaxDynamicSharedMemorySize, SMEMB);

    const int M = NNODES;
    const int mt = (M + 127) / 128;    // 782
    const int totalH = M * HDIM;
    const int total4 = totalH / 4;

    // ---- weight prep (single launch) ----
    {
        int tot = NW_IN + NLAYER * (NW_1 + NW_2);
        conv_w_all<<<(tot + 255) / 256, 256>>>(W_in, W1, W2, wh);
    }

    // ---- input projection: h16 = relu(x@W_in + b_in) fp16, agg = (1+eps0)*relu(...) ----
    tc_gemm<2, 0><<<dim3(2, mt), 256, SMEMB>>>(x, wh + WIN_OFF, b_in, h16, agg, eps, nullptr,
                                               M, HDIM, DIN);

    for (int l = 0; l < NLAYER; l++) {
        // agg[dst] += h[src]
        {
            long long tot = (long long)E * 64;
            scatter_kernel<<<(int)((tot + 255) / 256), 256>>>(h16, src, dst, agg, E);
        }
        // z1 = relu(agg @ W1_l + b1_l) -> fp16
        tc_gemm<1, 0><<<dim3(4, mt), 256, SMEMB>>>(agg, wh + W1_OFF + (size_t)l * H2 * HDIM,
                                                   b1 + (size_t)l * H2, z1, nullptr,
                                                   nullptr, nullptr, M, H2, HDIM);
        // z2 = z1 @ W2_l + b2_l (+ fused BN stats); A fp16 via cp.async
        cudaMemsetAsync(stats, 0, 2 * HDIM * sizeof(float));
        tc_gemm<3, 1><<<dim3(2, mt), 256, SMEMB>>>(z1, wh + W2_OFF + (size_t)l * HDIM * H2,
                                                   b2 + (size_t)l * HDIM, z2, nullptr,
                                                   nullptr, stats, M, HDIM, H2);
        // BN apply + relu
        if (l + 1 < NLAYER) {
            bn_apply_kernel<0><<<(total4 + 255) / 256, 256>>>(
                (const float4*)z2, stats, gamma + (size_t)l * HDIM, beta + (size_t)l * HDIM,
                eps + (l + 1), (uint2*)h16, (float4*)agg, nullptr, nullptr, total4);
        } else {
            cudaMemsetAsync(pool, 0, NGRAPH * HDIM * sizeof(float));
            cudaMemsetAsync(cnt, 0, NGRAPH * sizeof(float));
            count_kernel<<<(M + 255) / 256, 256>>>(batch, cnt, M);
            bn_apply_kernel<1><<<(total4 + 255) / 256, 256>>>(
                (const float4*)z2, stats, gamma + (size_t)l * HDIM, beta + (size_t)l * HDIM,
                nullptr, nullptr, nullptr, batch, pool, total4);
        }
    }

    // ---- head ----
    head_kernel<<<NGRAPH, 128>>>(pool, cnt, Wp1, bp1, Wp2, bp2, out);
}

// round 7
// speedup vs baseline: 2.5304x; 1.3354x over previous
#include <cuda_runtime.h>
#include <cuda_fp16.h>
#include <cstdint>

// ---------------- constants (problem-fixed) ----------------
#define NNODES 100000
#define NEDGES 300000
#define DIN    128
#define HDIM   256
#define H2     512
#define NLAYER 4
#define NGRAPH 512
#define BN_EPS 1e-5f

// ---------------- scratch (device globals; no allocation allowed) ----------------
__device__ __half g_h16[NNODES * HDIM];    // node features, fp16
__device__ __half g_agg16[NNODES * HDIM];  // (1+eps)h + neighbor sum, fp16
__device__ __half g_z1[NNODES * H2];       // MLP hidden, fp16
__device__ float g_z2[NNODES * HDIM];      // MLP out (pre-BN)
__device__ float g_stats[2 * HDIM];        // [sums | sumsq]
__device__ float g_pool[NGRAPH * HDIM];    // per-graph sums
__device__ float g_cnt[NGRAPH];            // per-graph counts
// CSR by destination
__device__ int g_deg[NNODES];
__device__ int g_rowptr[NNODES + 1];
__device__ int g_cursor[NNODES];
__device__ int g_ssrc[NEDGES];

// converted weights: transposed [N][K], fp16
#define WIN_OFF  0
#define W1_OFF   (256 * 128)
#define W2_OFF   (W1_OFF + NLAYER * 512 * 256)
#define WT_TOTAL (W2_OFF + NLAYER * 256 * 512)
__device__ __align__(16) __half g_wh[WT_TOTAL];

// ---------------- helpers ----------------
__device__ __forceinline__ uint32_t smem_u32(const void* p) {
    uint32_t a;
    asm("{ .reg .u64 t; cvta.to.shared.u64 t, %1; cvt.u32.u64 %0, t; }" : "=r"(a) : "l"(p));
    return a;
}
__device__ __forceinline__ uint32_t pkh(float a, float b) {
    __half2 t; t.x = __float2half(a); t.y = __float2half(b);
    return *reinterpret_cast<uint32_t*>(&t);
}
__device__ __forceinline__ uint32_t sw64(uint32_t off) {
    return off ^ ((off >> 3) & 0x30);
}
__device__ __forceinline__ void ldm4(uint32_t* r, uint32_t addr) {
    asm volatile("ldmatrix.sync.aligned.m8n8.x4.shared.b16 {%0,%1,%2,%3}, [%4];"
                 : "=r"(r[0]), "=r"(r[1]), "=r"(r[2]), "=r"(r[3]) : "r"(addr));
}
__device__ __forceinline__ void mma16816(float* c, const uint32_t* a, const uint32_t* b) {
    asm volatile("mma.sync.aligned.m16n8k16.row.col.f32.f16.f16.f32 "
                 "{%0,%1,%2,%3}, {%4,%5,%6,%7}, {%8,%9}, {%0,%1,%2,%3};"
                 : "+f"(c[0]), "+f"(c[1]), "+f"(c[2]), "+f"(c[3])
                 : "r"(a[0]), "r"(a[1]), "r"(a[2]), "r"(a[3]), "r"(b[0]), "r"(b[1]));
}

// smem stage: exact 64B rows + SW64 swizzle. A(8K) B(8K) = 16KB/stage.
#define T_A   0
#define T_B   8192
#define STAGE 16384
#define SMEMB (2 * STAGE + 128)

// ---------------- tensor-core GEMM via mma.sync fp16 ----------------
// C[M,N] = act(A[M,K] @ W[K,N] + bias); W fp16 [N][K].
// Block tile 128x128, K-chunk 32, 256 threads (warp tile 32x64), double-buffered, 2 CTAs/SM.
// AFP16: 0 = A fp32 (convert in-flight), 1 = A fp16 (cp.async).
// EPI: 1 = bias+relu -> fp16 C; 3 = bias -> fp32 C + fused BN stats.
template <int EPI, int AFP16>
__global__ __launch_bounds__(256, 2)
void tc_gemm(const void* __restrict__ Ap, const __half* __restrict__ Bh,
             const float* __restrict__ bias, void* __restrict__ Cp,
             float* __restrict__ stats, int M, int N, int K)
{
    extern __shared__ __align__(16) char smraw[];
    const uint32_t sb = (smem_u32(smraw) + 127) & ~127u;

    const int tid = threadIdx.x;
    const int lane = tid & 31, wid = tid >> 5;
    const int wm = (wid & 3) * 32;
    const int wn = (wid >> 2) * 64;
    const int bm = blockIdx.y * 128, bn = blockIdx.x * 128;
    const int nc = K / 32;

    float acc[2][8][4];
#pragma unroll
    for (int i = 0; i < 2; i++)
#pragma unroll
        for (int j = 0; j < 8; j++)
#pragma unroll
            for (int q = 0; q < 4; q++) acc[i][j][q] = 0.f;

    // ---- A load setup ----
    const float* af = (const float*)Ap;
    const __half* ah16 = (const __half*)Ap;
    // fp32 path: 2 threads per row, 16 floats each
    const int arow = tid >> 1;
    const int ahalf = tid & 1;
    int rga = bm + arow; if (rga >= M) rga = M - 1;
    const float* aptr = af + (size_t)rga * K + ahalf * 16;
    const uint32_t abase = (uint32_t)arow * 64 + (uint32_t)ahalf * 32;
    const uint32_t asw0 = sw64(abase);
    const uint32_t asw1 = sw64(abase + 16);
    // fp16 path: 512 x 16B segments, 2 per thread
    int arow0 = (tid * 2) >> 2, aseg0 = (tid * 2) & 3;
    int arow1 = (tid * 2 + 1) >> 2, aseg1 = (tid * 2 + 1) & 3;
    int rg0 = bm + arow0; if (rg0 >= M) rg0 = M - 1;
    int rg1 = bm + arow1; if (rg1 >= M) rg1 = M - 1;
    const uint32_t adst0 = sw64((uint32_t)arow0 * 64 + aseg0 * 16);
    const uint32_t adst1 = sw64((uint32_t)arow1 * 64 + aseg1 * 16);

    float4 ar[4];

#define LOAD_A_CHUNK(cc, stg)                                                            \
    do {                                                                                 \
        if (AFP16) {                                                                     \
            const __half* s0 = ah16 + (size_t)rg0 * K + (cc) * 32 + aseg0 * 8;           \
            const __half* s1 = ah16 + (size_t)rg1 * K + (cc) * 32 + aseg1 * 8;           \
            asm volatile("cp.async.ca.shared.global [%0], [%1], 16;" :: "r"((stg) + T_A + adst0), "l"(s0)); \
            asm volatile("cp.async.ca.shared.global [%0], [%1], 16;" :: "r"((stg) + T_A + adst1), "l"(s1)); \
        }                                                                                \
    } while (0)

#define CONV_A_CHUNK(stg)                                                                \
    do {                                                                                 \
        if (!AFP16) {                                                                    \
            _Pragma("unroll")                                                            \
            for (int j = 0; j < 4; j++) {                                                \
                float4 v = ar[j];                                                        \
                uint32_t h0 = pkh(v.x, v.y), h1 = pkh(v.z, v.w);                         \
                uint32_t sw = ((j >> 1) ? asw1 : asw0) + (j & 1) * 8;                    \
                asm volatile("st.shared.v2.b32 [%0], {%1,%2};" :: "r"((stg) + T_A + sw), "r"(h0), "r"(h1) : "memory"); \
            }                                                                            \
        }                                                                                \
    } while (0)

    // ---- prologue: chunk 0 ----
    if (!AFP16) {
#pragma unroll
        for (int j = 0; j < 4; j++) ar[j] = __ldg((const float4*)(aptr + 4 * j));
    }
    LOAD_A_CHUNK(0, sb);
#pragma unroll
    for (int i = 0; i < 2; i++) {
        int cc = tid + 256 * i;
        int row = cc >> 2, seg = cc & 3;
        const __half* src = Bh + (size_t)(bn + row) * K + seg * 8;
        uint32_t dst = sb + T_B + sw64((uint32_t)row * 64 + seg * 16);
        asm volatile("cp.async.ca.shared.global [%0], [%1], 16;" :: "r"(dst), "l"(src));
    }
    asm volatile("cp.async.commit_group;");
    CONV_A_CHUNK(sb);
    asm volatile("cp.async.wait_group 0;");
    __syncthreads();

    const uint32_t a_ro = (uint32_t)(lane & 15) * 64 + (uint32_t)(lane >> 4) * 16;
    const int brow = (lane & 7) + ((lane >> 4) << 3);
    const uint32_t b_ko = (uint32_t)((lane >> 3) & 1) * 16;

    for (int c = 0; c < nc; c++) {
        const uint32_t st0 = sb + (uint32_t)(c & 1) * STAGE;
        const uint32_t stn = sb + (uint32_t)((c + 1) & 1) * STAGE;
        const bool more = (c + 1 < nc);

        if (more) {
            if (!AFP16) {
#pragma unroll
                for (int j = 0; j < 4; j++) ar[j] = __ldg((const float4*)(aptr + (c + 1) * 32 + 4 * j));
            }
            LOAD_A_CHUNK(c + 1, stn);
#pragma unroll
            for (int i = 0; i < 2; i++) {
                int cc = tid + 256 * i;
                int row = cc >> 2, seg = cc & 3;
                const __half* src = Bh + (size_t)(bn + row) * K + (c + 1) * 32 + seg * 8;
                uint32_t dst = stn + T_B + sw64((uint32_t)row * 64 + seg * 16);
                asm volatile("cp.async.ca.shared.global [%0], [%1], 16;" :: "r"(dst), "l"(src));
            }
            asm volatile("cp.async.commit_group;");
        }

#pragma unroll
        for (int ks = 0; ks < 2; ks++) {
            uint32_t ah[2][4], bh[4][4];
#pragma unroll
            for (int mt = 0; mt < 2; mt++) {
                uint32_t off = (uint32_t)(wm + mt * 16) * 64 + a_ro + ks * 32;
                ldm4(ah[mt], st0 + T_A + sw64(off));
            }
#pragma unroll
            for (int g = 0; g < 4; g++) {
                uint32_t off = (uint32_t)(wn + g * 16 + brow) * 64 + ks * 32 + b_ko;
                ldm4(bh[g], st0 + T_B + sw64(off));
            }
#pragma unroll
            for (int mt = 0; mt < 2; mt++)
#pragma unroll
                for (int g = 0; g < 4; g++) {
                    mma16816(acc[mt][2 * g],     ah[mt], &bh[g][0]);
                    mma16816(acc[mt][2 * g + 1], ah[mt], &bh[g][2]);
                }
        }

        if (more) CONV_A_CHUNK(stn);
        asm volatile("cp.async.wait_group 0;");
        __syncthreads();
    }

    // ---- epilogue ----
    float* ssum = reinterpret_cast<float*>(smraw);        // [128]
    float* ssq  = reinterpret_cast<float*>(smraw) + 128;  // [128]
    if (EPI == 3) {
        if (tid < 256) reinterpret_cast<float*>(smraw)[tid] = 0.f;
        __syncthreads();
    }

    __half* Ch = (__half*)Cp;
    float*  Cf = (float*)Cp;
#pragma unroll
    for (int mt = 0; mt < 2; mt++) {
        int r0 = bm + wm + mt * 16 + (lane >> 2);
        int r1 = r0 + 8;
#pragma unroll
        for (int nt = 0; nt < 8; nt++) {
            int col = bn + wn + nt * 8 + (lane & 3) * 2;
            float2 bv = *reinterpret_cast<const float2*>(&bias[col]);
            float v0 = acc[mt][nt][0] + bv.x;
            float v1 = acc[mt][nt][1] + bv.y;
            float v2 = acc[mt][nt][2] + bv.x;
            float v3 = acc[mt][nt][3] + bv.y;
            if (EPI == 1) {
                v0 = fmaxf(v0, 0.f); v1 = fmaxf(v1, 0.f);
                v2 = fmaxf(v2, 0.f); v3 = fmaxf(v3, 0.f);
            }
            bool k0 = r0 < M, k1 = r1 < M;
            if (EPI == 1) {
                if (k0) *reinterpret_cast<uint32_t*>(&Ch[(size_t)r0 * N + col]) = pkh(v0, v1);
                if (k1) *reinterpret_cast<uint32_t*>(&Ch[(size_t)r1 * N + col]) = pkh(v2, v3);
            } else {
                if (k0) *reinterpret_cast<float2*>(&Cf[(size_t)r0 * N + col]) = make_float2(v0, v1);
                if (k1) *reinterpret_cast<float2*>(&Cf[(size_t)r1 * N + col]) = make_float2(v2, v3);
                float a0 = (k0 ? v0 : 0.f) + (k1 ? v2 : 0.f);
                float a1 = (k0 ? v1 : 0.f) + (k1 ? v3 : 0.f);
                float q0 = (k0 ? v0 * v0 : 0.f) + (k1 ? v2 * v2 : 0.f);
                float q1 = (k0 ? v1 * v1 : 0.f) + (k1 ? v3 * v3 : 0.f);
#pragma unroll
                for (int off = 16; off >= 4; off >>= 1) {
                    a0 += __shfl_xor_sync(0xffffffffu, a0, off);
                    a1 += __shfl_xor_sync(0xffffffffu, a1, off);
                    q0 += __shfl_xor_sync(0xffffffffu, q0, off);
                    q1 += __shfl_xor_sync(0xffffffffu, q1, off);
                }
                if (lane < 4) {
                    int lc = wn + nt * 8 + lane * 2;
                    atomicAdd(&ssum[lc], a0);
                    atomicAdd(&ssum[lc + 1], a1);
                    atomicAdd(&ssq[lc], q0);
                    atomicAdd(&ssq[lc + 1], q1);
                }
            }
        }
    }
    if (EPI == 3) {
        __syncthreads();
        if (tid < 128) {
            atomicAdd(&stats[bn + tid], ssum[tid]);
            atomicAdd(&stats[HDIM + bn + tid], ssq[tid]);
        }
    }
}

// ---------------- all-weight conversion (one launch) ----------------
#define NW_IN (128 * 256)
#define NW_1  (256 * 512)
#define NW_2  (512 * 256)
__global__ void conv_w_all(const float* __restrict__ W_in, const float* __restrict__ W1,
                           const float* __restrict__ W2, __half* __restrict__ wh)
{
    int idx = blockIdx.x * blockDim.x + threadIdx.x;
    if (idx < NW_IN) {
        int n = idx / 128, k = idx % 128;
        wh[WIN_OFF + idx] = __float2half(W_in[(size_t)k * 256 + n]);
    } else if (idx < NW_IN + NLAYER * NW_1) {
        int t = idx - NW_IN;
        int l = t / NW_1, r = t % NW_1;
        int n = r / 256, k = r % 256;
        wh[W1_OFF + t] = __float2half(W1[(size_t)l * NW_1 + (size_t)k * 512 + n]);
    } else if (idx < NW_IN + NLAYER * (NW_1 + NW_2)) {
        int t = idx - NW_IN - NLAYER * NW_1;
        int l = t / NW_2, r = t % NW_2;
        int n = r / 512, k = r % 512;
        wh[W2_OFF + t] = __float2half(W2[(size_t)l * NW_2 + (size_t)k * 256 + n]);
    }
}

// ---------------- CSR build ----------------
__global__ void hist_kernel(const int* __restrict__ dst, int* __restrict__ deg, int E)
{
    int i = blockIdx.x * blockDim.x + threadIdx.x;
    if (i < E) atomicAdd(&deg[__ldg(&dst[i])], 1);
}

// single-block exclusive scan over NNODES -> rowptr[N+1]
__global__ void scan_kernel(const int* __restrict__ deg, int* __restrict__ rowptr)
{
    __shared__ int buf[1024];
    __shared__ int carry;
    int tid = threadIdx.x;
    if (tid == 0) carry = 0;
    __syncthreads();
    for (int base = 0; base < NNODES; base += 1024) {
        int v = (base + tid < NNODES) ? deg[base + tid] : 0;
        buf[tid] = v;
        __syncthreads();
#pragma unroll
        for (int off = 1; off < 1024; off <<= 1) {
            int t = (tid >= off) ? buf[tid - off] : 0;
            __syncthreads();
            buf[tid] += t;
            __syncthreads();
        }
        if (base + tid < NNODES) rowptr[base + tid + 1] = carry + buf[tid];
        __syncthreads();
        if (tid == 0) carry += buf[1023];
        __syncthreads();
    }
    if (tid == 0) rowptr[0] = 0;
}

__global__ void fill_kernel(const int* __restrict__ src, const int* __restrict__ dst,
                            int* __restrict__ cursor, int* __restrict__ ssrc, int E)
{
    int i = blockIdx.x * blockDim.x + threadIdx.x;
    if (i >= E) return;
    int pos = atomicAdd(&cursor[__ldg(&dst[i])], 1);
    ssrc[pos] = __ldg(&src[i]);
}

// ---------------- aggregate: agg16[d] = fp16((1+eps)*h[d] + sum_{src->d} h[src]) ----------------
// one warp per node; lane owns 8 channels (16B).
__global__ void aggregate_kernel(const __half* __restrict__ h, const int* __restrict__ rowptr,
                                 const int* __restrict__ ssrc, const float* __restrict__ epsp,
                                 __half* __restrict__ agg)
{
    int warp = (blockIdx.x * blockDim.x + threadIdx.x) >> 5;
    int lane = threadIdx.x & 31;
    if (warp >= NNODES) return;
    int beg = __ldg(&rowptr[warp]);
    int end = __ldg(&rowptr[warp + 1]);
    float e = 1.0f + __ldg(epsp);

    float a[8];
    {
        uint4 v = __ldg(reinterpret_cast<const uint4*>(&h[(size_t)warp * HDIM + lane * 8]));
        const __half2* p = reinterpret_cast<const __half2*>(&v);
#pragma unroll
        for (int q = 0; q < 4; q++) {
            float2 f = __half22float2(p[q]);
            a[2 * q] = e * f.x;
            a[2 * q + 1] = e * f.y;
        }
    }
    int j = beg;
    for (; j + 1 < end; j += 2) {
        int s0 = __ldg(&ssrc[j]);
        int s1 = __ldg(&ssrc[j + 1]);
        uint4 v0 = __ldg(reinterpret_cast<const uint4*>(&h[(size_t)s0 * HDIM + lane * 8]));
        uint4 v1 = __ldg(reinterpret_cast<const uint4*>(&h[(size_t)s1 * HDIM + lane * 8]));
        const __half2* p0 = reinterpret_cast<const __half2*>(&v0);
        const __half2* p1 = reinterpret_cast<const __half2*>(&v1);
#pragma unroll
        for (int q = 0; q < 4; q++) {
            float2 f0 = __half22float2(p0[q]);
            float2 f1 = __half22float2(p1[q]);
            a[2 * q] += f0.x + f1.x;
            a[2 * q + 1] += f0.y + f1.y;
        }
    }
    if (j < end) {
        int s0 = __ldg(&ssrc[j]);
        uint4 v0 = __ldg(reinterpret_cast<const uint4*>(&h[(size_t)s0 * HDIM + lane * 8]));
        const __half2* p0 = reinterpret_cast<const __half2*>(&v0);
#pragma unroll
        for (int q = 0; q < 4; q++) {
            float2 f0 = __half22float2(p0[q]);
            a[2 * q] += f0.x;
            a[2 * q + 1] += f0.y;
        }
    }
    uint4 o;
    uint32_t* ow = reinterpret_cast<uint32_t*>(&o);
#pragma unroll
    for (int q = 0; q < 4; q++) ow[q] = pkh(a[2 * q], a[2 * q + 1]);
    *reinterpret_cast<uint4*>(&agg[(size_t)warp * HDIM + lane * 8]) = o;
}

// ---------------- BN apply + relu ----------------
// POOL=0: write h16 (fp16). POOL=1: per-graph pool atomics only.
template <int POOL>
__global__ void bn_apply_kernel(const float4* __restrict__ z, const float* __restrict__ stats,
                                const float* __restrict__ gamma, const float* __restrict__ beta,
                                uint2* __restrict__ h16,
                                const int* __restrict__ batch, float* __restrict__ pool,
                                int total4)
{
    int i = blockIdx.x * blockDim.x + threadIdx.x;
    if (i >= total4) return;
    int c = (i << 2) & (HDIM - 1);
    const float invN = 1.0f / (float)NNODES;
    float4 s = *reinterpret_cast<const float4*>(&stats[c]);
    float4 q = *reinterpret_cast<const float4*>(&stats[HDIM + c]);
    float4 g = *reinterpret_cast<const float4*>(&gamma[c]);
    float4 b = *reinterpret_cast<const float4*>(&beta[c]);
    float4 zv = z[i];
    float4 r;
    {
        float mu = s.x * invN, var = q.x * invN - mu * mu;
        r.x = fmaxf((zv.x - mu) * (g.x * rsqrtf(var + BN_EPS)) + b.x, 0.f);
    }
    {
        float mu = s.y * invN, var = q.y * invN - mu * mu;
        r.y = fmaxf((zv.y - mu) * (g.y * rsqrtf(var + BN_EPS)) + b.y, 0.f);
    }
    {
        float mu = s.z * invN, var = q.z * invN - mu * mu;
        r.z = fmaxf((zv.z - mu) * (g.z * rsqrtf(var + BN_EPS)) + b.z, 0.f);
    }
    {
        float mu = s.w * invN, var = q.w * invN - mu * mu;
        r.w = fmaxf((zv.w - mu) * (g.w * rsqrtf(var + BN_EPS)) + b.w, 0.f);
    }
    if (POOL == 0) {
        uint2 p;
        p.x = pkh(r.x, r.y);
        p.y = pkh(r.z, r.w);
        h16[i] = p;
    } else {
        int node = i >> 6;
        int gidx = __ldg(&batch[node]);
        float* o = &pool[(size_t)gidx * HDIM + c];
        atomicAdd(o + 0, r.x);
        atomicAdd(o + 1, r.y);
        atomicAdd(o + 2, r.z);
        atomicAdd(o + 3, r.w);
    }
}

// ---------------- per-graph node counts ----------------
__global__ void count_kernel(const int* __restrict__ batch, float* __restrict__ cnt, int n)
{
    int i = blockIdx.x * blockDim.x + threadIdx.x;
    if (i < n) atomicAdd(&cnt[__ldg(&batch[i])], 1.0f);
}

// ---------------- predictor head ----------------
__global__ void head_kernel(const float* __restrict__ pooled, const float* __restrict__ cnt,
                            const float* __restrict__ Wp1, const float* __restrict__ bp1,
                            const float* __restrict__ Wp2, const float* __restrict__ bp2,
                            float* __restrict__ out)
{
    __shared__ float sp[HDIM];
    __shared__ float red[128];
    int g = blockIdx.x;
    int tid = threadIdx.x;   // 128 threads
    float inv = 1.0f / fmaxf(__ldg(&cnt[g]), 1.0f);
    for (int k = tid; k < HDIM; k += 128)
        sp[k] = pooled[(size_t)g * HDIM + k] * inv;
    __syncthreads();

    float s = __ldg(&bp1[tid]);
#pragma unroll 4
    for (int k = 0; k < HDIM; k++)
        s = fmaf(sp[k], __ldg(&Wp1[k * 128 + tid]), s);
    s = fmaxf(s, 0.f);
    float t = s * __ldg(&Wp2[tid]);

    red[tid] = t;
    __syncthreads();
    for (int off = 64; off > 0; off >>= 1) {
        if (tid < off) red[tid] += red[tid + off];
        __syncthreads();
    }
    if (tid == 0) out[g] = red[0] + __ldg(&bp2[0]);
}

// ---------------- host launch ----------------
static void* sym_addr(const void* symbol)
{
    void* p = nullptr;
    cudaGetSymbolAddress(&p, symbol);
    return p;
}

extern "C" void kernel_launch(void* const* d_in, const int* in_sizes, int n_in,
                              void* d_out, int out_size)
{
    const float* x      = (const float*)d_in[0];
    const int*   ei     = (const int*)d_in[1];
    const int*   batch  = (const int*)d_in[2];
    const float* W_in   = (const float*)d_in[3];
    const float* b_in   = (const float*)d_in[4];
    const float* eps    = (const float*)d_in[5];
    const float* W1     = (const float*)d_in[6];
    const float* b1     = (const float*)d_in[7];
    const float* W2     = (const float*)d_in[8];
    const float* b2     = (const float*)d_in[9];
    const float* gamma  = (const float*)d_in[10];
    const float* beta   = (const float*)d_in[11];
    const float* Wp1    = (const float*)d_in[12];
    const float* bp1    = (const float*)d_in[13];
    const float* Wp2    = (const float*)d_in[14];
    const float* bp2    = (const float*)d_in[15];
    float* out = (float*)d_out;

    const int E = in_sizes[1] / 2;
    const int* src = ei;
    const int* dst = ei + E;

    __half* h16   = (__half*)sym_addr(g_h16);
    __half* agg16 = (__half*)sym_addr(g_agg16);
    __half* z1    = (__half*)sym_addr(g_z1);
    float* z2     = (float*)sym_addr(g_z2);
    float* stats  = (float*)sym_addr(g_stats);
    float* pool   = (float*)sym_addr(g_pool);
    float* cnt    = (float*)sym_addr(g_cnt);
    __half* wh    = (__half*)sym_addr(g_wh);
    int* deg      = (int*)sym_addr(g_deg);
    int* rowptr   = (int*)sym_addr(g_rowptr);
    int* cursor   = (int*)sym_addr(g_cursor);
    int* ssrc     = (int*)sym_addr(g_ssrc);

    cudaFuncSetAttribute((const void*)tc_gemm<1, 0>, cudaFuncAttributeMaxDynamicSharedMemorySize, SMEMB);
    cudaFuncSetAttribute((const void*)tc_gemm<1, 1>, cudaFuncAttributeMaxDynamicSharedMemorySize, SMEMB);
    cudaFuncSetAttribute((const void*)tc_gemm<3, 1>, cudaFuncAttributeMaxDynamicSharedMemorySize, SMEMB);

    const int M = NNODES;
    const int mt = (M + 127) / 128;    // 782
    const int totalH = M * HDIM;
    const int total4 = totalH / 4;

    // ---- weight prep ----
    {
        int tot = NW_IN + NLAYER * (NW_1 + NW_2);
        conv_w_all<<<(tot + 255) / 256, 256>>>(W_in, W1, W2, wh);
    }

    // ---- CSR build (by dst) ----
    cudaMemsetAsync(deg, 0, NNODES * sizeof(int));
    hist_kernel<<<(E + 255) / 256, 256>>>(dst, deg, E);
    scan_kernel<<<1, 1024>>>(deg, rowptr);
    cudaMemcpyAsync(cursor, rowptr, NNODES * sizeof(int), cudaMemcpyDeviceToDevice);
    fill_kernel<<<(E + 255) / 256, 256>>>(src, dst, cursor, ssrc, E);

    // ---- input projection: h16 = relu(x@W_in + b_in) ----
    tc_gemm<1, 0><<<dim3(2, mt), 256, SMEMB>>>(x, wh + WIN_OFF, b_in, h16, nullptr,
                                               M, HDIM, DIN);

    for (int l = 0; l < NLAYER; l++) {
        // agg16 = (1+eps_l)*h + gather-sum
        aggregate_kernel<<<(NNODES * 32 + 255) / 256, 256>>>(h16, rowptr, ssrc, eps + l, agg16);
        // z1 = relu(agg16 @ W1_l + b1_l) -> fp16
        tc_gemm<1, 1><<<dim3(4, mt), 256, SMEMB>>>(agg16, wh + W1_OFF + (size_t)l * H2 * HDIM,
                                                   b1 + (size_t)l * H2, z1, nullptr,
                                                   M, H2, HDIM);
        // z2 = z1 @ W2_l + b2_l (+ fused BN stats)
        cudaMemsetAsync(stats, 0, 2 * HDIM * sizeof(float));
        tc_gemm<3, 1><<<dim3(2, mt), 256, SMEMB>>>(z1, wh + W2_OFF + (size_t)l * HDIM * H2,
                                                   b2 + (size_t)l * HDIM, z2, stats,
                                                   M, HDIM, H2);
        // BN apply + relu
        if (l + 1 < NLAYER) {
            bn_apply_kernel<0><<<(total4 + 255) / 256, 256>>>(
                (const float4*)z2, stats, gamma + (size_t)l * HDIM, beta + (size_t)l * HDIM,
                (uint2*)h16, nullptr, nullptr, total4);
        } else {
            cudaMemsetAsync(pool, 0, NGRAPH * HDIM * sizeof(float));
            cudaMemsetAsync(cnt, 0, NGRAPH * sizeof(float));
            count_kernel<<<(M + 255) / 256, 256>>>(batch, cnt, M);
            bn_apply_kernel<1><<<(total4 + 255) / 256, 256>>>(
                (const float4*)z2, stats, gamma + (size_t)l * HDIM, beta + (size_t)l * HDIM,
                nullptr, batch, pool, total4);
        }
    }

    // ---- head ----
    head_kernel<<<NGRAPH, 128>>>(pool, cnt, Wp1, bp1, Wp2, bp2, out);
}

// round 9
// speedup vs baseline: 2.6869x; 1.0618x over previous
#include <cuda_runtime.h>
#include <cuda_fp16.h>
#include <cstdint>

// ---------------- constants (problem-fixed) ----------------
#define NNODES 100000
#define NEDGES 300000
#define DIN    128
#define HDIM   256
#define H2     512
#define NLAYER 4
#define NGRAPH 512
#define BN_EPS 1e-5f

// ---------------- scratch (device globals; no allocation allowed) ----------------
__device__ __half g_h16[NNODES * HDIM];    // node features, fp16
__device__ __half g_agg16[NNODES * HDIM];  // (1+eps)h + neighbor sum, fp16
__device__ __half g_z1[NNODES * H2];       // MLP hidden, fp16
__device__ float g_z2[NNODES * HDIM];      // MLP out (pre-BN)
__device__ float g_stats[2 * HDIM];        // [sums | sumsq]
__device__ float g_pool[NGRAPH * HDIM];    // per-graph sums
__device__ float g_cnt[NGRAPH];            // per-graph counts
// CSR by destination
__device__ int g_deg[NNODES];
__device__ int g_rowptr[NNODES + 1];
__device__ int g_cursor[NNODES];
__device__ int g_ssrc[NEDGES];

// converted weights: transposed [N][K], fp16
#define WIN_OFF  0
#define W1_OFF   (256 * 128)
#define W2_OFF   (W1_OFF + NLAYER * 512 * 256)
#define WT_TOTAL (W2_OFF + NLAYER * 256 * 512)
__device__ __align__(16) __half g_wh[WT_TOTAL];

// ---------------- helpers ----------------
__device__ __forceinline__ uint32_t smem_u32(const void* p) {
    uint32_t a;
    asm("{ .reg .u64 t; cvta.to.shared.u64 t, %1; cvt.u32.u64 %0, t; }" : "=r"(a) : "l"(p));
    return a;
}
__device__ __forceinline__ uint32_t pkh(float a, float b) {
    __half2 t; t.x = __float2half(a); t.y = __float2half(b);
    return *reinterpret_cast<uint32_t*>(&t);
}
__device__ __forceinline__ uint32_t sw64(uint32_t off) {
    return off ^ ((off >> 3) & 0x30);
}
__device__ __forceinline__ void ldm4(uint32_t* r, uint32_t addr) {
    asm volatile("ldmatrix.sync.aligned.m8n8.x4.shared.b16 {%0,%1,%2,%3}, [%4];"
                 : "=r"(r[0]), "=r"(r[1]), "=r"(r[2]), "=r"(r[3]) : "r"(addr));
}
__device__ __forceinline__ void mma16816(float* c, const uint32_t* a, const uint32_t* b) {
    asm volatile("mma.sync.aligned.m16n8k16.row.col.f32.f16.f16.f32 "
                 "{%0,%1,%2,%3}, {%4,%5,%6,%7}, {%8,%9}, {%0,%1,%2,%3};"
                 : "+f"(c[0]), "+f"(c[1]), "+f"(c[2]), "+f"(c[3])
                 : "r"(a[0]), "r"(a[1]), "r"(a[2]), "r"(a[3]), "r"(b[0]), "r"(b[1]));
}

// smem: exact 64B rows + SW64 swizzle. A(8K) B(8K) = 16KB/stage, 3 stages.
#define T_A    0
#define T_B    8192
#define STAGE  16384
#define NSTG   3
#define SMEMB  (NSTG * STAGE + 256)

// ---------------- tensor-core GEMM via mma.sync fp16 ----------------
// C[M,N] = act(A[M,K] @ W[K,N] + bias); W fp16 [N][K].
// Block tile 128x128, 128 threads: 4 warps (2x2), warp tile 64x64.
// 3-stage cp.async pipeline (race-free: issue only after post-compute barrier), 2 CTAs/SM.
// AFP16: 0 = A fp32 (LDG + convert); 1 = A fp16 (cp.async).
// EPI: 1 = bias+relu -> fp16 C; 3 = bias -> fp32 C + fused BN stats.
template <int EPI, int AFP16>
__global__ __launch_bounds__(128, 2)
void tc_gemm(const void* __restrict__ Ap, const __half* __restrict__ Bh,
             const float* __restrict__ bias, void* __restrict__ Cp,
             float* __restrict__ stats, int M, int N, int K)
{
    extern __shared__ __align__(16) char smraw[];
    const uint32_t sb = (smem_u32(smraw) + 127) & ~127u;

    const int tid = threadIdx.x;
    const int lane = tid & 31, wid = tid >> 5;
    const int wm = (wid & 1) * 64;       // 2 warps in M
    const int wn = (wid >> 1) * 64;      // 2 warps in N
    const int bm = blockIdx.y * 128, bn = blockIdx.x * 128;
    const int nc = K / 32;

    float acc[4][8][4];
#pragma unroll
    for (int i = 0; i < 4; i++)
#pragma unroll
        for (int j = 0; j < 8; j++)
#pragma unroll
            for (int q = 0; q < 4; q++) acc[i][j][q] = 0.f;

    // ---- A fp32 path: one row per thread (32 floats per chunk) ----
    const float* af = (const float*)Ap;
    const __half* ah16 = (const __half*)Ap;
    int rga = bm + tid; if (rga >= M) rga = M - 1;
    const float* aptr = af + (size_t)rga * K;
    uint32_t asw[4];
#pragma unroll
    for (int q = 0; q < 4; q++) asw[q] = sw64((uint32_t)tid * 64 + q * 16);

    // ---- A/B fp16 cp.async path: 4 x 16B segments per thread ----
    int argv[4]; uint32_t adst[4];
    int brgv[4]; uint32_t bdst[4];
#pragma unroll
    for (int j = 0; j < 4; j++) {
        int s = tid + 128 * j;
        int row = s >> 2, seg = s & 3;
        uint32_t d = sw64((uint32_t)row * 64 + seg * 16);
        int ra = bm + row; if (ra >= M) ra = M - 1;
        argv[j] = ra; adst[j] = d;
        brgv[j] = bn + row; bdst[j] = d;
    }

    float4 ar[8];

#define ISSUE_STAGE(cc, stg)                                                              \
    do {                                                                                  \
        if (AFP16) {                                                                      \
            _Pragma("unroll")                                                             \
            for (int j = 0; j < 4; j++) {                                                 \
                int s = tid + 128 * j;                                                    \
                const __half* sp = ah16 + (size_t)argv[j] * K + (cc) * 32 + (s & 3) * 8;  \
                asm volatile("cp.async.ca.shared.global [%0], [%1], 16;"                  \
                             :: "r"((stg) + T_A + adst[j]), "l"(sp));                     \
            }                                                                             \
        }                                                                                 \
        _Pragma("unroll")                                                                 \
        for (int j = 0; j < 4; j++) {                                                     \
            int s = tid + 128 * j;                                                        \
            const __half* sp = Bh + (size_t)brgv[j] * K + (cc) * 32 + (s & 3) * 8;        \
            asm volatile("cp.async.ca.shared.global [%0], [%1], 16;"                      \
                         :: "r"((stg) + T_B + bdst[j]), "l"(sp));                         \
        }                                                                                 \
        asm volatile("cp.async.commit_group;");                                           \
    } while (0)

#define LDG_A(cc)                                                                         \
    do {                                                                                  \
        if (!AFP16 && (cc) < nc) {                                                        \
            _Pragma("unroll")                                                             \
            for (int j = 0; j < 8; j++) ar[j] = __ldg((const float4*)(aptr + (cc) * 32 + 4 * j)); \
        }                                                                                 \
    } while (0)

#define STS_A(stg)                                                                        \
    do {                                                                                  \
        if (!AFP16) {                                                                     \
            _Pragma("unroll")                                                             \
            for (int q = 0; q < 4; q++) {                                                 \
                float4 v0 = ar[2 * q], v1 = ar[2 * q + 1];                                \
                uint32_t p0 = pkh(v0.x, v0.y), p1 = pkh(v0.z, v0.w);                      \
                uint32_t p2 = pkh(v1.x, v1.y), p3 = pkh(v1.z, v1.w);                      \
                asm volatile("st.shared.v4.b32 [%0], {%1,%2,%3,%4};"                      \
                             :: "r"((stg) + T_A + asw[q]), "r"(p0), "r"(p1), "r"(p2), "r"(p3) : "memory"); \
            }                                                                             \
        }                                                                                 \
    } while (0)

    // ---- prologue ----
    LDG_A(0);
    ISSUE_STAGE(0, sb);
    if (nc > 1) ISSUE_STAGE(1, sb + STAGE);
    STS_A(sb);          // A chunk 0 (fp32 path)
    LDG_A(1);           // regs for chunk 1 (fp32 path)
    if (nc > 1) { asm volatile("cp.async.wait_group 1;"); }
    else        { asm volatile("cp.async.wait_group 0;"); }
    __syncthreads();    // stage 0 ready for all warps

    // ldmatrix per-lane address components
    const uint32_t a_ro = (uint32_t)(lane & 15) * 64 + (uint32_t)(lane >> 4) * 16;
    const int brow = (lane & 7) + ((lane >> 4) << 3);
    const uint32_t b_ko = (uint32_t)((lane >> 3) & 1) * 16;

    for (int c = 0; c < nc; c++) {
        const uint32_t st0 = sb + (uint32_t)(c % NSTG) * STAGE;

        // ---- compute chunk c (stage ready & synced) ----
#pragma unroll
        for (int ks = 0; ks < 2; ks++) {
            uint32_t ahf[4][4], bhf[4][4];
#pragma unroll
            for (int mt = 0; mt < 4; mt++) {
                uint32_t off = (uint32_t)(wm + mt * 16) * 64 + a_ro + ks * 32;
                ldm4(ahf[mt], st0 + T_A + sw64(off));
            }
#pragma unroll
            for (int g = 0; g < 4; g++) {
                uint32_t off = (uint32_t)(wn + g * 16 + brow) * 64 + ks * 32 + b_ko;
                ldm4(bhf[g], st0 + T_B + sw64(off));
            }
#pragma unroll
            for (int mt = 0; mt < 4; mt++)
#pragma unroll
                for (int g = 0; g < 4; g++) {
                    mma16816(acc[mt][2 * g],     ahf[mt], &bhf[g][0]);
                    mma16816(acc[mt][2 * g + 1], ahf[mt], &bhf[g][2]);
                }
        }

        if (c + 1 < nc) {
            // fp32 path: store A chunk c+1 into its stage (only this thread's rows; other
            // warps are still reading stage c's A — different stage, safe)
            STS_A(sb + (uint32_t)((c + 1) % NSTG) * STAGE);
            // barrier 1: every warp done with compute(c) (and a fortiori compute(c-1))
            __syncthreads();
            // now stage (c+2)%NSTG == (c-1)%NSTG is free: issue its loads
            LDG_A(c + 2);
            if (c + 2 < nc) {
                ISSUE_STAGE(c + 2, sb + (uint32_t)((c + 2) % NSTG) * STAGE);
                asm volatile("cp.async.wait_group 1;");
            } else {
                asm volatile("cp.async.wait_group 0;");
            }
            // barrier 2: stage c+1 data (cp.async B/A + STS A) visible to all warps
            __syncthreads();
        }
    }

    // ---- epilogue ----
    float* ssum = reinterpret_cast<float*>(smraw);        // [128]
    float* ssq  = reinterpret_cast<float*>(smraw) + 128;  // [128]
    if (EPI == 3) {
        __syncthreads();   // all warps done reading smem stages (overlaps stats area)
        ssum[tid] = 0.f;
        ssq[tid] = 0.f;
        __syncthreads();
    }

    __half* Ch = (__half*)Cp;
    float*  Cf = (float*)Cp;
#pragma unroll
    for (int mt = 0; mt < 4; mt++) {
        int r0 = bm + wm + mt * 16 + (lane >> 2);
        int r1 = r0 + 8;
#pragma unroll
        for (int nt = 0; nt < 8; nt++) {
            int col = bn + wn + nt * 8 + (lane & 3) * 2;
            float2 bv = *reinterpret_cast<const float2*>(&bias[col]);
            float v0 = acc[mt][nt][0] + bv.x;
            float v1 = acc[mt][nt][1] + bv.y;
            float v2 = acc[mt][nt][2] + bv.x;
            float v3 = acc[mt][nt][3] + bv.y;
            if (EPI == 1) {
                v0 = fmaxf(v0, 0.f); v1 = fmaxf(v1, 0.f);
                v2 = fmaxf(v2, 0.f); v3 = fmaxf(v3, 0.f);
            }
            bool k0 = r0 < M, k1 = r1 < M;
            if (EPI == 1) {
                if (k0) *reinterpret_cast<uint32_t*>(&Ch[(size_t)r0 * N + col]) = pkh(v0, v1);
                if (k1) *reinterpret_cast<uint32_t*>(&Ch[(size_t)r1 * N + col]) = pkh(v2, v3);
            } else {
                if (k0) *reinterpret_cast<float2*>(&Cf[(size_t)r0 * N + col]) = make_float2(v0, v1);
                if (k1) *reinterpret_cast<float2*>(&Cf[(size_t)r1 * N + col]) = make_float2(v2, v3);
                float a0 = (k0 ? v0 : 0.f) + (k1 ? v2 : 0.f);
                float a1 = (k0 ? v1 : 0.f) + (k1 ? v3 : 0.f);
                float q0 = (k0 ? v0 * v0 : 0.f) + (k1 ? v2 * v2 : 0.f);
                float q1 = (k0 ? v1 * v1 : 0.f) + (k1 ? v3 * v3 : 0.f);
#pragma unroll
                for (int off = 16; off >= 4; off >>= 1) {
                    a0 += __shfl_xor_sync(0xffffffffu, a0, off);
                    a1 += __shfl_xor_sync(0xffffffffu, a1, off);
                    q0 += __shfl_xor_sync(0xffffffffu, q0, off);
                    q1 += __shfl_xor_sync(0xffffffffu, q1, off);
                }
                if (lane < 4) {
                    int lc = wn + nt * 8 + lane * 2;
                    atomicAdd(&ssum[lc], a0);
                    atomicAdd(&ssum[lc + 1], a1);
                    atomicAdd(&ssq[lc], q0);
                    atomicAdd(&ssq[lc + 1], q1);
                }
            }
        }
    }
    if (EPI == 3) {
        __syncthreads();
        atomicAdd(&stats[bn + tid], ssum[tid]);
        atomicAdd(&stats[HDIM + bn + tid], ssq[tid]);
    }
}

// ---------------- all-weight conversion (one launch) ----------------
#define NW_IN (128 * 256)
#define NW_1  (256 * 512)
#define NW_2  (512 * 256)
__global__ void conv_w_all(const float* __restrict__ W_in, const float* __restrict__ W1,
                           const float* __restrict__ W2, __half* __restrict__ wh)
{
    int idx = blockIdx.x * blockDim.x + threadIdx.x;
    if (idx < NW_IN) {
        int n = idx / 128, k = idx % 128;
        wh[WIN_OFF + idx] = __float2half(W_in[(size_t)k * 256 + n]);
    } else if (idx < NW_IN + NLAYER * NW_1) {
        int t = idx - NW_IN;
        int l = t / NW_1, r = t % NW_1;
        int n = r / 256, k = r % 256;
        wh[W1_OFF + t] = __float2half(W1[(size_t)l * NW_1 + (size_t)k * 512 + n]);
    } else if (idx < NW_IN + NLAYER * (NW_1 + NW_2)) {
        int t = idx - NW_IN - NLAYER * NW_1;
        int l = t / NW_2, r = t % NW_2;
        int n = r / 512, k = r % 512;
        wh[W2_OFF + t] = __float2half(W2[(size_t)l * NW_2 + (size_t)k * 256 + n]);
    }
}

// ---------------- CSR build ----------------
__global__ void hist_kernel(const int* __restrict__ dst, int* __restrict__ deg, int E)
{
    int i = blockIdx.x * blockDim.x + threadIdx.x;
    if (i < E) atomicAdd(&deg[__ldg(&dst[i])], 1);
}

__global__ void scan_kernel(const int* __restrict__ deg, int* __restrict__ rowptr)
{
    __shared__ int buf[1024];
    __shared__ int carry;
    int tid = threadIdx.x;
    if (tid == 0) carry = 0;
    __syncthreads();
    for (int base = 0; base < NNODES; base += 1024) {
        int v = (base + tid < NNODES) ? deg[base + tid] : 0;
        buf[tid] = v;
        __syncthreads();
#pragma unroll
        for (int off = 1; off < 1024; off <<= 1) {
            int t = (tid >= off) ? buf[tid - off] : 0;
            __syncthreads();
            buf[tid] += t;
            __syncthreads();
        }
        if (base + tid < NNODES) rowptr[base + tid + 1] = carry + buf[tid];
        __syncthreads();
        if (tid == 0) carry += buf[1023];
        __syncthreads();
    }
    if (tid == 0) rowptr[0] = 0;
}

__global__ void fill_kernel(const int* __restrict__ src, const int* __restrict__ dst,
                            int* __restrict__ cursor, int* __restrict__ ssrc, int E)
{
    int i = blockIdx.x * blockDim.x + threadIdx.x;
    if (i >= E) return;
    int pos = atomicAdd(&cursor[__ldg(&dst[i])], 1);
    ssrc[pos] = __ldg(&src[i]);
}

// ---------------- aggregate: agg16[d] = fp16((1+eps)*h[d] + sum_{src->d} h[src]) ----------------
__global__ void aggregate_kernel(const __half* __restrict__ h, const int* __restrict__ rowptr,
                                 const int* __restrict__ ssrc, const float* __restrict__ epsp,
                                 __half* __restrict__ agg)
{
    int warp = (blockIdx.x * blockDim.x + threadIdx.x) >> 5;
    int lane = threadIdx.x & 31;
    if (warp >= NNODES) return;
    int beg = __ldg(&rowptr[warp]);
    int end = __ldg(&rowptr[warp + 1]);
    float e = 1.0f + __ldg(epsp);

    float a[8];
    {
        uint4 v = __ldg(reinterpret_cast<const uint4*>(&h[(size_t)warp * HDIM + lane * 8]));
        const __half2* p = reinterpret_cast<const __half2*>(&v);
#pragma unroll
        for (int q = 0; q < 4; q++) {
            float2 f = __half22float2(p[q]);
            a[2 * q] = e * f.x;
            a[2 * q + 1] = e * f.y;
        }
    }
    int j = beg;
    for (; j + 1 < end; j += 2) {
        int s0 = __ldg(&ssrc[j]);
        int s1 = __ldg(&ssrc[j + 1]);
        uint4 v0 = __ldg(reinterpret_cast<const uint4*>(&h[(size_t)s0 * HDIM + lane * 8]));
        uint4 v1 = __ldg(reinterpret_cast<const uint4*>(&h[(size_t)s1 * HDIM + lane * 8]));
        const __half2* p0 = reinterpret_cast<const __half2*>(&v0);
        const __half2* p1 = reinterpret_cast<const __half2*>(&v1);
#pragma unroll
        for (int q = 0; q < 4; q++) {
            float2 f0 = __half22float2(p0[q]);
            float2 f1 = __half22float2(p1[q]);
            a[2 * q] += f0.x + f1.x;
            a[2 * q + 1] += f0.y + f1.y;
        }
    }
    if (j < end) {
        int s0 = __ldg(&ssrc[j]);
        uint4 v0 = __ldg(reinterpret_cast<const uint4*>(&h[(size_t)s0 * HDIM + lane * 8]));
        const __half2* p0 = reinterpret_cast<const __half2*>(&v0);
#pragma unroll
        for (int q = 0; q < 4; q++) {
            float2 f0 = __half22float2(p0[q]);
            a[2 * q] += f0.x;
            a[2 * q + 1] += f0.y;
        }
    }
    uint4 o;
    uint32_t* ow = reinterpret_cast<uint32_t*>(&o);
#pragma unroll
    for (int q = 0; q < 4; q++) ow[q] = pkh(a[2 * q], a[2 * q + 1]);
    *reinterpret_cast<uint4*>(&agg[(size_t)warp * HDIM + lane * 8]) = o;
}

// ---------------- BN apply + relu ----------------
template <int POOL>
__global__ void bn_apply_kernel(const float4* __restrict__ z, const float* __restrict__ stats,
                                const float* __restrict__ gamma, const float* __restrict__ beta,
                                uint2* __restrict__ h16,
                                const int* __restrict__ batch, float* __restrict__ pool,
                                int total4)
{
    int i = blockIdx.x * blockDim.x + threadIdx.x;
    if (i >= total4) return;
    int c = (i << 2) & (HDIM - 1);
    const float invN = 1.0f / (float)NNODES;
    float4 s = *reinterpret_cast<const float4*>(&stats[c]);
    float4 q = *reinterpret_cast<const float4*>(&stats[HDIM + c]);
    float4 g = *reinterpret_cast<const float4*>(&gamma[c]);
    float4 b = *reinterpret_cast<const float4*>(&beta[c]);
    float4 zv = z[i];
    float4 r;
    {
        float mu = s.x * invN, var = q.x * invN - mu * mu;
        r.x = fmaxf((zv.x - mu) * (g.x * rsqrtf(var + BN_EPS)) + b.x, 0.f);
    }
    {
        float mu = s.y * invN, var = q.y * invN - mu * mu;
        r.y = fmaxf((zv.y - mu) * (g.y * rsqrtf(var + BN_EPS)) + b.y, 0.f);
    }
    {
        float mu = s.z * invN, var = q.z * invN - mu * mu;
        r.z = fmaxf((zv.z - mu) * (g.z * rsqrtf(var + BN_EPS)) + b.z, 0.f);
    }
    {
        float mu = s.w * invN, var = q.w * invN - mu * mu;
        r.w = fmaxf((zv.w - mu) * (g.w * rsqrtf(var + BN_EPS)) + b.w, 0.f);
    }
    if (POOL == 0) {
        uint2 p;
        p.x = pkh(r.x, r.y);
        p.y = pkh(r.z, r.w);
        h16[i] = p;
    } else {
        int node = i >> 6;
        int gidx = __ldg(&batch[node]);
        float* o = &pool[(size_t)gidx * HDIM + c];
        atomicAdd(o + 0, r.x);
        atomicAdd(o + 1, r.y);
        atomicAdd(o + 2, r.z);
        atomicAdd(o + 3, r.w);
    }
}

// ---------------- per-graph node counts ----------------
__global__ void count_kernel(const int* __restrict__ batch, float* __restrict__ cnt, int n)
{
    int i = blockIdx.x * blockDim.x + threadIdx.x;
    if (i < n) atomicAdd(&cnt[__ldg(&batch[i])], 1.0f);
}

// ---------------- predictor head ----------------
__global__ void head_kernel(const float* __restrict__ pooled, const float* __restrict__ cnt,
                            const float* __restrict__ Wp1, const float* __restrict__ bp1,
                            const float* __restrict__ Wp2, const float* __restrict__ bp2,
                            float* __restrict__ out)
{
    __shared__ float sp[HDIM];
    __shared__ float red[128];
    int g = blockIdx.x;
    int tid = threadIdx.x;   // 128 threads
    float inv = 1.0f / fmaxf(__ldg(&cnt[g]), 1.0f);
    for (int k = tid; k < HDIM; k += 128)
        sp[k] = pooled[(size_t)g * HDIM + k] * inv;
    __syncthreads();

    float s = __ldg(&bp1[tid]);
#pragma unroll 4
    for (int k = 0; k < HDIM; k++)
        s = fmaf(sp[k], __ldg(&Wp1[k * 128 + tid]), s);
    s = fmaxf(s, 0.f);
    float t = s * __ldg(&Wp2[tid]);

    red[tid] = t;
    __syncthreads();
    for (int off = 64; off > 0; off >>= 1) {
        if (tid < off) red[tid] += red[tid + off];
        __syncthreads();
    }
    if (tid == 0) out[g] = red[0] + __ldg(&bp2[0]);
}

// ---------------- host launch ----------------
static void* sym_addr(const void* symbol)
{
    void* p = nullptr;
    cudaGetSymbolAddress(&p, symbol);
    return p;
}

extern "C" void kernel_launch(void* const* d_in, const int* in_sizes, int n_in,
                              void* d_out, int out_size)
{
    const float* x      = (const float*)d_in[0];
    const int*   ei     = (const int*)d_in[1];
    const int*   batch  = (const int*)d_in[2];
    const float* W_in   = (const float*)d_in[3];
    const float* b_in   = (const float*)d_in[4];
    const float* eps    = (const float*)d_in[5];
    const float* W1     = (const float*)d_in[6];
    const float* b1     = (const float*)d_in[7];
    const float* W2     = (const float*)d_in[8];
    const float* b2     = (const float*)d_in[9];
    const float* gamma  = (const float*)d_in[10];
    const float* beta   = (const float*)d_in[11];
    const float* Wp1    = (const float*)d_in[12];
    const float* bp1    = (const float*)d_in[13];
    const float* Wp2    = (const float*)d_in[14];
    const float* bp2    = (const float*)d_in[15];
    float* out = (float*)d_out;

    const int E = in_sizes[1] / 2;
    const int* src = ei;
    const int* dst = ei + E;

    __half* h16   = (__half*)sym_addr(g_h16);
    __half* agg16 = (__half*)sym_addr(g_agg16);
    __half* z1    = (__half*)sym_addr(g_z1);
    float* z2     = (float*)sym_addr(g_z2);
    float* stats  = (float*)sym_addr(g_stats);
    float* pool   = (float*)sym_addr(g_pool);
    float* cnt    = (float*)sym_addr(g_cnt);
    __half* wh    = (__half*)sym_addr(g_wh);
    int* deg      = (int*)sym_addr(g_deg);
    int* rowptr   = (int*)sym_addr(g_rowptr);
    int* cursor   = (int*)sym_addr(g_cursor);
    int* ssrc     = (int*)sym_addr(g_ssrc);

    cudaFuncSetAttribute((const void*)tc_gemm<1, 0>, cudaFuncAttributeMaxDynamicSharedMemorySize, SMEMB);
    cudaFuncSetAttribute((const void*)tc_gemm<1, 1>, cudaFuncAttributeMaxDynamicSharedMemorySize, SMEMB);
    cudaFuncSetAttribute((const void*)tc_gemm<3, 1>, cudaFuncAttributeMaxDynamicSharedMemorySize, SMEMB);

    const int M = NNODES;
    const int mt = (M + 127) / 128;    // 782
    const int totalH = M * HDIM;
    const int total4 = totalH / 4;

    // ---- weight prep ----
    {
        int tot = NW_IN + NLAYER * (NW_1 + NW_2);
        conv_w_all<<<(tot + 255) / 256, 256>>>(W_in, W1, W2, wh);
    }

    // ---- CSR build (by dst) ----
    cudaMemsetAsync(deg, 0, NNODES * sizeof(int));
    hist_kernel<<<(E + 255) / 256, 256>>>(dst, deg, E);
    scan_kernel<<<1, 1024>>>(deg, rowptr);
    cudaMemcpyAsync(cursor, rowptr, NNODES * sizeof(int), cudaMemcpyDeviceToDevice);
    fill_kernel<<<(E + 255) / 256, 256>>>(src, dst, cursor, ssrc, E);

    // ---- input projection: h16 = relu(x@W_in + b_in) ----
    tc_gemm<1, 0><<<dim3(2, mt), 128, SMEMB>>>(x, wh + WIN_OFF, b_in, h16, nullptr,
                                               M, HDIM, DIN);

    for (int l = 0; l < NLAYER; l++) {
        // agg16 = (1+eps_l)*h + gather-sum
        aggregate_kernel<<<(NNODES * 32 + 255) / 256, 256>>>(h16, rowptr, ssrc, eps + l, agg16);
        // z1 = relu(agg16 @ W1_l + b1_l) -> fp16
        tc_gemm<1, 1><<<dim3(4, mt), 128, SMEMB>>>(agg16, wh + W1_OFF + (size_t)l * H2 * HDIM,
                                                   b1 + (size_t)l * H2, z1, nullptr,
                                                   M, H2, HDIM);
        // z2 = z1 @ W2_l + b2_l (+ fused BN stats)
        cudaMemsetAsync(stats, 0, 2 * HDIM * sizeof(float));
        tc_gemm<3, 1><<<dim3(2, mt), 128, SMEMB>>>(z1, wh + W2_OFF + (size_t)l * HDIM * H2,
                                                   b2 + (size_t)l * HDIM, z2, stats,
                                                   M, HDIM, H2);
        // BN apply + relu
        if (l + 1 < NLAYER) {
            bn_apply_kernel<0><<<(total4 + 255) / 256, 256>>>(
                (const float4*)z2, stats, gamma + (size_t)l * HDIM, beta + (size_t)l * HDIM,
                (uint2*)h16, nullptr, nullptr, total4);
        } else {
            cudaMemsetAsync(pool, 0, NGRAPH * HDIM * sizeof(float));
            cudaMemsetAsync(cnt, 0, NGRAPH * sizeof(float));
            count_kernel<<<(M + 255) / 256, 256>>>(batch, cnt, M);
            bn_apply_kernel<1><<<(total4 + 255) / 256, 256>>>(
                (const float4*)z2, stats, gamma + (size_t)l * HDIM, beta + (size_t)l * HDIM,
                nullptr, batch, pool, total4);
        }
    }

    // ---- head ----
    head_kernel<<<NGRAPH, 128>>>(pool, cnt, Wp1, bp1, Wp2, bp2, out);
}

// round 10
// speedup vs baseline: 2.8498x; 1.0606x over previous
#include <cuda_runtime.h>
#include <cuda_fp16.h>
#include <cstdint>

// ---------------- constants (problem-fixed) ----------------
#define NNODES 100000
#define NEDGES 300000
#define DIN    128
#define HDIM   256
#define H2     512
#define NLAYER 4
#define NGRAPH 512
#define BN_EPS 1e-5f

// ---------------- scratch (device globals; no allocation allowed) ----------------
__device__ __half g_x16[NNODES * DIN];     // input features, fp16
__device__ __half g_h16[NNODES * HDIM];    // node features, fp16
__device__ __half g_agg16[NNODES * HDIM];  // (1+eps)h + neighbor sum, fp16
__device__ __half g_z1[NNODES * H2];       // MLP hidden, fp16
__device__ __half g_z2[NNODES * HDIM];     // MLP out (pre-BN), fp16
__device__ float g_stats[2 * HDIM];        // [sums | sumsq]
__device__ float g_pool[NGRAPH * HDIM];    // per-graph sums
__device__ float g_cnt[NGRAPH];            // per-graph counts
// CSR by destination
__device__ int g_deg[NNODES];
__device__ int g_rowptr[NNODES + 1];
__device__ int g_cursor[NNODES];
__device__ int g_ssrc[NEDGES];

// converted weights: transposed [N][K], fp16
#define WIN_OFF  0
#define W1_OFF   (256 * 128)
#define W2_OFF   (W1_OFF + NLAYER * 512 * 256)
#define WT_TOTAL (W2_OFF + NLAYER * 256 * 512)
__device__ __align__(16) __half g_wh[WT_TOTAL];

// ---------------- helpers ----------------
__device__ __forceinline__ uint32_t smem_u32(const void* p) {
    uint32_t a;
    asm("{ .reg .u64 t; cvta.to.shared.u64 t, %1; cvt.u32.u64 %0, t; }" : "=r"(a) : "l"(p));
    return a;
}
__device__ __forceinline__ uint32_t pkh(float a, float b) {
    __half2 t; t.x = __float2half(a); t.y = __float2half(b);
    return *reinterpret_cast<uint32_t*>(&t);
}
__device__ __forceinline__ uint32_t sw128(uint32_t off) {
    return off ^ ((off >> 3) & 0x70);
}
__device__ __forceinline__ void ldm4(uint32_t* r, uint32_t addr) {
    asm volatile("ldmatrix.sync.aligned.m8n8.x4.shared.b16 {%0,%1,%2,%3}, [%4];"
                 : "=r"(r[0]), "=r"(r[1]), "=r"(r[2]), "=r"(r[3]) : "r"(addr));
}
__device__ __forceinline__ void mma16816(float* c, const uint32_t* a, const uint32_t* b) {
    asm volatile("mma.sync.aligned.m16n8k16.row.col.f32.f16.f16.f32 "
                 "{%0,%1,%2,%3}, {%4,%5,%6,%7}, {%8,%9}, {%0,%1,%2,%3};"
                 : "+f"(c[0]), "+f"(c[1]), "+f"(c[2]), "+f"(c[3])
                 : "r"(a[0]), "r"(a[1]), "r"(a[2]), "r"(a[3]), "r"(b[0]), "r"(b[1]));
}

// smem stage: 128 rows x 128B (SW128) per operand. A(16K) B(16K) = 32KB/stage, 3 stages.
#define T_A    0
#define T_B    16384
#define STAGE  32768
#define NSTG   3
#define SMEMB  (NSTG * STAGE + 256)

// ---------------- tensor-core GEMM via mma.sync fp16 ----------------
// C[M,N] = act(A[M,K]fp16 @ W[K,N] + bias); W fp16 [N][K]; A fp16 row-major.
// Block tile 128x128, 128 threads: 4 warps (2x2), warp tile 64x64, K-chunk 64.
// 3-stage cp.async pipeline (race-free), 2 CTAs/SM.
// EPI: 1 = bias+relu -> fp16 C; 3 = bias -> fp16 C + fused fp32 BN stats.
template <int EPI>
__global__ __launch_bounds__(128, 2)
void tc_gemm(const __half* __restrict__ A, const __half* __restrict__ Bh,
             const float* __restrict__ bias, __half* __restrict__ C,
             float* __restrict__ stats, int M, int N, int K)
{
    extern __shared__ __align__(16) char smraw[];
    const uint32_t sb = (smem_u32(smraw) + 127) & ~127u;

    const int tid = threadIdx.x;
    const int lane = tid & 31, wid = tid >> 5;
    const int wm = (wid & 1) * 64;       // 2 warps in M
    const int wn = (wid >> 1) * 64;      // 2 warps in N
    const int bm = blockIdx.y * 128, bn = blockIdx.x * 128;
    const int nc = K / 64;

    float acc[4][8][4];
#pragma unroll
    for (int i = 0; i < 4; i++)
#pragma unroll
        for (int j = 0; j < 8; j++)
#pragma unroll
            for (int q = 0; q < 4; q++) acc[i][j][q] = 0.f;

// issue one stage (chunk cc) of A+B loads: 8 x 16B segments each per thread
#define ISSUE_STAGE(cc, stg)                                                              \
    do {                                                                                  \
        _Pragma("unroll")                                                                 \
        for (int j = 0; j < 8; j++) {                                                     \
            int s = tid + 128 * j;                                                        \
            int row = s >> 3, seg = s & 7;                                                \
            uint32_t d = sw128((uint32_t)row * 128 + seg * 16);                           \
            int ra = bm + row; if (ra >= M) ra = M - 1;                                   \
            const __half* pa = A + (size_t)ra * K + (cc) * 64 + seg * 8;                  \
            asm volatile("cp.async.ca.shared.global [%0], [%1], 16;"                      \
                         :: "r"((stg) + T_A + d), "l"(pa));                               \
            const __half* pb = Bh + (size_t)(bn + row) * K + (cc) * 64 + seg * 8;         \
            asm volatile("cp.async.ca.shared.global [%0], [%1], 16;"                      \
                         :: "r"((stg) + T_B + d), "l"(pb));                               \
        }                                                                                 \
        asm volatile("cp.async.commit_group;");                                           \
    } while (0)

    // ---- prologue ----
    ISSUE_STAGE(0, sb);
    if (nc > 1) ISSUE_STAGE(1, sb + STAGE);
    if (nc > 1) { asm volatile("cp.async.wait_group 1;"); }
    else        { asm volatile("cp.async.wait_group 0;"); }
    __syncthreads();    // stage 0 ready for all warps

    // ldmatrix per-lane address components (128B rows)
    const uint32_t a_ro = (uint32_t)(lane & 15) * 128 + (uint32_t)(lane >> 4) * 16;
    const int brow = (lane & 7) + ((lane >> 4) << 3);
    const uint32_t b_ko = (uint32_t)((lane >> 3) & 1) * 16;

    for (int c = 0; c < nc; c++) {
        const uint32_t st0 = sb + (uint32_t)(c % NSTG) * STAGE;

        // ---- compute chunk c: 4 k16 steps ----
#pragma unroll
        for (int ks = 0; ks < 4; ks++) {
            uint32_t ahf[4][4], bhf[4][4];
#pragma unroll
            for (int mt = 0; mt < 4; mt++) {
                uint32_t off = (uint32_t)(wm + mt * 16) * 128 + a_ro + ks * 32;
                ldm4(ahf[mt], st0 + T_A + sw128(off));
            }
#pragma unroll
            for (int g = 0; g < 4; g++) {
                uint32_t off = (uint32_t)(wn + g * 16 + brow) * 128 + ks * 32 + b_ko;
                ldm4(bhf[g], st0 + T_B + sw128(off));
            }
#pragma unroll
            for (int mt = 0; mt < 4; mt++)
#pragma unroll
                for (int g = 0; g < 4; g++) {
                    mma16816(acc[mt][2 * g],     ahf[mt], &bhf[g][0]);
                    mma16816(acc[mt][2 * g + 1], ahf[mt], &bhf[g][2]);
                }
        }

        if (c + 1 < nc) {
            // barrier 1: every warp done with compute(c) — stage (c+2)%3 == (c-1)%3 free
            __syncthreads();
            if (c + 2 < nc) {
                ISSUE_STAGE(c + 2, sb + (uint32_t)((c + 2) % NSTG) * STAGE);
                asm volatile("cp.async.wait_group 1;");
            } else {
                asm volatile("cp.async.wait_group 0;");
            }
            // barrier 2: stage c+1 data visible to all warps
            __syncthreads();
        }
    }

    // ---- epilogue ----
    float* ssum = reinterpret_cast<float*>(smraw);        // [128]
    float* ssq  = reinterpret_cast<float*>(smraw) + 128;  // [128]
    if (EPI == 3) {
        __syncthreads();   // all warps done reading smem stages (overlaps stats area)
        ssum[tid] = 0.f;
        ssq[tid] = 0.f;
        __syncthreads();
    }

#pragma unroll
    for (int mt = 0; mt < 4; mt++) {
        int r0 = bm + wm + mt * 16 + (lane >> 2);
        int r1 = r0 + 8;
#pragma unroll
        for (int nt = 0; nt < 8; nt++) {
            int col = bn + wn + nt * 8 + (lane & 3) * 2;
            float2 bv = *reinterpret_cast<const float2*>(&bias[col]);
            float v0 = acc[mt][nt][0] + bv.x;
            float v1 = acc[mt][nt][1] + bv.y;
            float v2 = acc[mt][nt][2] + bv.x;
            float v3 = acc[mt][nt][3] + bv.y;
            if (EPI == 1) {
                v0 = fmaxf(v0, 0.f); v1 = fmaxf(v1, 0.f);
                v2 = fmaxf(v2, 0.f); v3 = fmaxf(v3, 0.f);
            }
            bool k0 = r0 < M, k1 = r1 < M;
            if (k0) *reinterpret_cast<uint32_t*>(&C[(size_t)r0 * N + col]) = pkh(v0, v1);
            if (k1) *reinterpret_cast<uint32_t*>(&C[(size_t)r1 * N + col]) = pkh(v2, v3);
            if (EPI == 3) {
                float a0 = (k0 ? v0 : 0.f) + (k1 ? v2 : 0.f);
                float a1 = (k0 ? v1 : 0.f) + (k1 ? v3 : 0.f);
                float q0 = (k0 ? v0 * v0 : 0.f) + (k1 ? v2 * v2 : 0.f);
                float q1 = (k0 ? v1 * v1 : 0.f) + (k1 ? v3 * v3 : 0.f);
#pragma unroll
                for (int off = 16; off >= 4; off >>= 1) {
                    a0 += __shfl_xor_sync(0xffffffffu, a0, off);
                    a1 += __shfl_xor_sync(0xffffffffu, a1, off);
                    q0 += __shfl_xor_sync(0xffffffffu, q0, off);
                    q1 += __shfl_xor_sync(0xffffffffu, q1, off);
                }
                if (lane < 4) {
                    int lc = wn + nt * 8 + lane * 2;
                    atomicAdd(&ssum[lc], a0);
                    atomicAdd(&ssum[lc + 1], a1);
                    atomicAdd(&ssq[lc], q0);
                    atomicAdd(&ssq[lc + 1], q1);
                }
            }
        }
    }
    if (EPI == 3) {
        __syncthreads();
        atomicAdd(&stats[bn + tid], ssum[tid]);
        atomicAdd(&stats[HDIM + bn + tid], ssq[tid]);
    }
}

// ---------------- input conversion: x fp32 -> fp16 ----------------
__global__ void conv_x(const float4* __restrict__ x, uint2* __restrict__ x16, int total4)
{
    int i = blockIdx.x * blockDim.x + threadIdx.x;
    if (i >= total4) return;
    float4 v = x[i];
    uint2 p;
    p.x = pkh(v.x, v.y);
    p.y = pkh(v.z, v.w);
    x16[i] = p;
}

// ---------------- all-weight conversion (one launch) ----------------
#define NW_IN (128 * 256)
#define NW_1  (256 * 512)
#define NW_2  (512 * 256)
__global__ void conv_w_all(const float* __restrict__ W_in, const float* __restrict__ W1,
                           const float* __restrict__ W2, __half* __restrict__ wh)
{
    int idx = blockIdx.x * blockDim.x + threadIdx.x;
    if (idx < NW_IN) {
        int n = idx / 128, k = idx % 128;
        wh[WIN_OFF + idx] = __float2half(W_in[(size_t)k * 256 + n]);
    } else if (idx < NW_IN + NLAYER * NW_1) {
        int t = idx - NW_IN;
        int l = t / NW_1, r = t % NW_1;
        int n = r / 256, k = r % 256;
        wh[W1_OFF + t] = __float2half(W1[(size_t)l * NW_1 + (size_t)k * 512 + n]);
    } else if (idx < NW_IN + NLAYER * (NW_1 + NW_2)) {
        int t = idx - NW_IN - NLAYER * NW_1;
        int l = t / NW_2, r = t % NW_2;
        int n = r / 512, k = r % 512;
        wh[W2_OFF + t] = __float2half(W2[(size_t)l * NW_2 + (size_t)k * 256 + n]);
    }
}

// ---------------- CSR build ----------------
__global__ void hist_kernel(const int* __restrict__ dst, int* __restrict__ deg, int E)
{
    int i = blockIdx.x * blockDim.x + threadIdx.x;
    if (i < E) atomicAdd(&deg[__ldg(&dst[i])], 1);
}

__global__ void scan_kernel(const int* __restrict__ deg, int* __restrict__ rowptr)
{
    __shared__ int buf[1024];
    __shared__ int carry;
    int tid = threadIdx.x;
    if (tid == 0) carry = 0;
    __syncthreads();
    for (int base = 0; base < NNODES; base += 1024) {
        int v = (base + tid < NNODES) ? deg[base + tid] : 0;
        buf[tid] = v;
        __syncthreads();
#pragma unroll
        for (int off = 1; off < 1024; off <<= 1) {
            int t = (tid >= off) ? buf[tid - off] : 0;
            __syncthreads();
            buf[tid] += t;
            __syncthreads();
        }
        if (base + tid < NNODES) rowptr[base + tid + 1] = carry + buf[tid];
        __syncthreads();
        if (tid == 0) carry += buf[1023];
        __syncthreads();
    }
    if (tid == 0) rowptr[0] = 0;
}

__global__ void fill_kernel(const int* __restrict__ src, const int* __restrict__ dst,
                            int* __restrict__ cursor, int* __restrict__ ssrc, int E)
{
    int i = blockIdx.x * blockDim.x + threadIdx.x;
    if (i >= E) return;
    int pos = atomicAdd(&cursor[__ldg(&dst[i])], 1);
    ssrc[pos] = __ldg(&src[i]);
}

// ---------------- aggregate: agg16[d] = fp16((1+eps)*h[d] + sum_{src->d} h[src]) ----------------
__global__ void aggregate_kernel(const __half* __restrict__ h, const int* __restrict__ rowptr,
                                 const int* __restrict__ ssrc, const float* __restrict__ epsp,
                                 __half* __restrict__ agg)
{
    int warp = (blockIdx.x * blockDim.x + threadIdx.x) >> 5;
    int lane = threadIdx.x & 31;
    if (warp >= NNODES) return;
    int beg = __ldg(&rowptr[warp]);
    int end = __ldg(&rowptr[warp + 1]);
    float e = 1.0f + __ldg(epsp);

    float a[8];
    {
        uint4 v = __ldg(reinterpret_cast<const uint4*>(&h[(size_t)warp * HDIM + lane * 8]));
        const __half2* p = reinterpret_cast<const __half2*>(&v);
#pragma unroll
        for (int q = 0; q < 4; q++) {
            float2 f = __half22float2(p[q]);
            a[2 * q] = e * f.x;
            a[2 * q + 1] = e * f.y;
        }
    }
    int j = beg;
    for (; j + 1 < end; j += 2) {
        int s0 = __ldg(&ssrc[j]);
        int s1 = __ldg(&ssrc[j + 1]);
        uint4 v0 = __ldg(reinterpret_cast<const uint4*>(&h[(size_t)s0 * HDIM + lane * 8]));
        uint4 v1 = __ldg(reinterpret_cast<const uint4*>(&h[(size_t)s1 * HDIM + lane * 8]));
        const __half2* p0 = reinterpret_cast<const __half2*>(&v0);
        const __half2* p1 = reinterpret_cast<const __half2*>(&v1);
#pragma unroll
        for (int q = 0; q < 4; q++) {
            float2 f0 = __half22float2(p0[q]);
            float2 f1 = __half22float2(p1[q]);
            a[2 * q] += f0.x + f1.x;
            a[2 * q + 1] += f0.y + f1.y;
        }
    }
    if (j < end) {
        int s0 = __ldg(&ssrc[j]);
        uint4 v0 = __ldg(reinterpret_cast<const uint4*>(&h[(size_t)s0 * HDIM + lane * 8]));
        const __half2* p0 = reinterpret_cast<const __half2*>(&v0);
#pragma unroll
        for (int q = 0; q < 4; q++) {
            float2 f0 = __half22float2(p0[q]);
            a[2 * q] += f0.x;
            a[2 * q + 1] += f0.y;
        }
    }
    uint4 o;
    uint32_t* ow = reinterpret_cast<uint32_t*>(&o);
#pragma unroll
    for (int q = 0; q < 4; q++) ow[q] = pkh(a[2 * q], a[2 * q + 1]);
    *reinterpret_cast<uint4*>(&agg[(size_t)warp * HDIM + lane * 8]) = o;
}

// ---------------- BN apply + relu (z2 fp16) ----------------
// POOL=0: write h16 (fp16). POOL=1: per-graph pool atomics only.
template <int POOL>
__global__ void bn_apply_kernel(const uint2* __restrict__ z, const float* __restrict__ stats,
                                const float* __restrict__ gamma, const float* __restrict__ beta,
                                uint2* __restrict__ h16,
                                const int* __restrict__ batch, float* __restrict__ pool,
                                int total4)
{
    int i = blockIdx.x * blockDim.x + threadIdx.x;
    if (i >= total4) return;
    int c = (i << 2) & (HDIM - 1);
    const float invN = 1.0f / (float)NNODES;
    float4 s = *reinterpret_cast<const float4*>(&stats[c]);
    float4 q = *reinterpret_cast<const float4*>(&stats[HDIM + c]);
    float4 g = *reinterpret_cast<const float4*>(&gamma[c]);
    float4 b = *reinterpret_cast<const float4*>(&beta[c]);
    uint2 zp = z[i];
    float2 z01 = __half22float2(*reinterpret_cast<const __half2*>(&zp.x));
    float2 z23 = __half22float2(*reinterpret_cast<const __half2*>(&zp.y));
    float4 r;
    {
        float mu = s.x * invN, var = q.x * invN - mu * mu;
        r.x = fmaxf((z01.x - mu) * (g.x * rsqrtf(var + BN_EPS)) + b.x, 0.f);
    }
    {
        float mu = s.y * invN, var = q.y * invN - mu * mu;
        r.y = fmaxf((z01.y - mu) * (g.y * rsqrtf(var + BN_EPS)) + b.y, 0.f);
    }
    {
        float mu = s.z * invN, var = q.z * invN - mu * mu;
        r.z = fmaxf((z23.x - mu) * (g.z * rsqrtf(var + BN_EPS)) + b.z, 0.f);
    }
    {
        float mu = s.w * invN, var = q.w * invN - mu * mu;
        r.w = fmaxf((z23.y - mu) * (g.w * rsqrtf(var + BN_EPS)) + b.w, 0.f);
    }
    if (POOL == 0) {
        uint2 p;
        p.x = pkh(r.x, r.y);
        p.y = pkh(r.z, r.w);
        h16[i] = p;
    } else {
        int node = i >> 6;
        int gidx = __ldg(&batch[node]);
        float* o = &pool[(size_t)gidx * HDIM + c];
        atomicAdd(o + 0, r.x);
        atomicAdd(o + 1, r.y);
        atomicAdd(o + 2, r.z);
        atomicAdd(o + 3, r.w);
    }
}

// ---------------- per-graph node counts ----------------
__global__ void count_kernel(const int* __restrict__ batch, float* __restrict__ cnt, int n)
{
    int i = blockIdx.x * blockDim.x + threadIdx.x;
    if (i < n) atomicAdd(&cnt[__ldg(&batch[i])], 1.0f);
}

// ---------------- predictor head ----------------
__global__ void head_kernel(const float* __restrict__ pooled, const float* __restrict__ cnt,
                            const float* __restrict__ Wp1, const float* __restrict__ bp1,
                            const float* __restrict__ Wp2, const float* __restrict__ bp2,
                            float* __restrict__ out)
{
    __shared__ float sp[HDIM];
    __shared__ float red[128];
    int g = blockIdx.x;
    int tid = threadIdx.x;   // 128 threads
    float inv = 1.0f / fmaxf(__ldg(&cnt[g]), 1.0f);
    for (int k = tid; k < HDIM; k += 128)
        sp[k] = pooled[(size_t)g * HDIM + k] * inv;
    __syncthreads();

    float s = __ldg(&bp1[tid]);
#pragma unroll 4
    for (int k = 0; k < HDIM; k++)
        s = fmaf(sp[k], __ldg(&Wp1[k * 128 + tid]), s);
    s = fmaxf(s, 0.f);
    float t = s * __ldg(&Wp2[tid]);

    red[tid] = t;
    __syncthreads();
    for (int off = 64; off > 0; off >>= 1) {
        if (tid < off) red[tid] += red[tid + off];
        __syncthreads();
    }
    if (tid == 0) out[g] = red[0] + __ldg(&bp2[0]);
}

// ---------------- host launch ----------------
static void* sym_addr(const void* symbol)
{
    void* p = nullptr;
    cudaGetSymbolAddress(&p, symbol);
    return p;
}

extern "C" void kernel_launch(void* const* d_in, const int* in_sizes, int n_in,
                              void* d_out, int out_size)
{
    const float* x      = (const float*)d_in[0];
    const int*   ei     = (const int*)d_in[1];
    const int*   batch  = (const int*)d_in[2];
    const float* W_in   = (const float*)d_in[3];
    const float* b_in   = (const float*)d_in[4];
    const float* eps    = (const float*)d_in[5];
    const float* W1     = (const float*)d_in[6];
    const float* b1     = (const float*)d_in[7];
    const float* W2     = (const float*)d_in[8];
    const float* b2     = (const float*)d_in[9];
    const float* gamma  = (const float*)d_in[10];
    const float* beta   = (const float*)d_in[11];
    const float* Wp1    = (const float*)d_in[12];
    const float* bp1    = (const float*)d_in[13];
    const float* Wp2    = (const float*)d_in[14];
    const float* bp2    = (const float*)d_in[15];
    float* out = (float*)d_out;

    const int E = in_sizes[1] / 2;
    const int* src = ei;
    const int* dst = ei + E;

    __half* x16   = (__half*)sym_addr(g_x16);
    __half* h16   = (__half*)sym_addr(g_h16);
    __half* agg16 = (__half*)sym_addr(g_agg16);
    __half* z1    = (__half*)sym_addr(g_z1);
    __half* z2    = (__half*)sym_addr(g_z2);
    float* stats  = (float*)sym_addr(g_stats);
    float* pool   = (float*)sym_addr(g_pool);
    float* cnt    = (float*)sym_addr(g_cnt);
    __half* wh    = (__half*)sym_addr(g_wh);
    int* deg      = (int*)sym_addr(g_deg);
    int* rowptr   = (int*)sym_addr(g_rowptr);
    int* cursor   = (int*)sym_addr(g_cursor);
    int* ssrc     = (int*)sym_addr(g_ssrc);

    cudaFuncSetAttribute((const void*)tc_gemm<1>, cudaFuncAttributeMaxDynamicSharedMemorySize, SMEMB);
    cudaFuncSetAttribute((const void*)tc_gemm<3>, cudaFuncAttributeMaxDynamicSharedMemorySize, SMEMB);

    const int M = NNODES;
    const int mt = (M + 127) / 128;    // 782
    const int totalH = M * HDIM;
    const int total4 = totalH / 4;

    // ---- weight + input prep ----
    {
        int tot = NW_IN + NLAYER * (NW_1 + NW_2);
        conv_w_all<<<(tot + 255) / 256, 256>>>(W_in, W1, W2, wh);
    }
    conv_x<<<(M * DIN / 4 + 255) / 256, 256>>>((const float4*)x, (uint2*)x16, M * DIN / 4);

    // ---- CSR build (by dst) ----
    cudaMemsetAsync(deg, 0, NNODES * sizeof(int));
    hist_kernel<<<(E + 255) / 256, 256>>>(dst, deg, E);
    scan_kernel<<<1, 1024>>>(deg, rowptr);
    cudaMemcpyAsync(cursor, rowptr, NNODES * sizeof(int), cudaMemcpyDeviceToDevice);
    fill_kernel<<<(E + 255) / 256, 256>>>(src, dst, cursor, ssrc, E);

    // ---- input projection: h16 = relu(x16 @ W_in + b_in) ----
    tc_gemm<1><<<dim3(2, mt), 128, SMEMB>>>(x16, wh + WIN_OFF, b_in, h16, nullptr,
                                            M, HDIM, DIN);

    for (int l = 0; l < NLAYER; l++) {
        // agg16 = (1+eps_l)*h + gather-sum
        aggregate_kernel<<<(NNODES * 32 + 255) / 256, 256>>>(h16, rowptr, ssrc, eps + l, agg16);
        // z1 = relu(agg16 @ W1_l + b1_l) -> fp16
        tc_gemm<1><<<dim3(4, mt), 128, SMEMB>>>(agg16, wh + W1_OFF + (size_t)l * H2 * HDIM,
                                                b1 + (size_t)l * H2, z1, nullptr,
                                                M, H2, HDIM);
        // z2 = z1 @ W2_l + b2_l (fp16) + fused fp32 BN stats
        cudaMemsetAsync(stats, 0, 2 * HDIM * sizeof(float));
        tc_gemm<3><<<dim3(2, mt), 128, SMEMB>>>(z1, wh + W2_OFF + (size_t)l * HDIM * H2,
                                                b2 + (size_t)l * HDIM, z2, stats,
                                                M, HDIM, H2);
        // BN apply + relu
        if (l + 1 < NLAYER) {
            bn_apply_kernel<0><<<(total4 + 255) / 256, 256>>>(
                (const uint2*)z2, stats, gamma + (size_t)l * HDIM, beta + (size_t)l * HDIM,
                (uint2*)h16, nullptr, nullptr, total4);
        } else {
            cudaMemsetAsync(pool, 0, NGRAPH * HDIM * sizeof(float));
            cudaMemsetAsync(cnt, 0, NGRAPH * sizeof(float));
            count_kernel<<<(M + 255) / 256, 256>>>(batch, cnt, M);
            bn_apply_kernel<1><<<(total4 + 255) / 256, 256>>>(
                (const uint2*)z2, stats, gamma + (size_t)l * HDIM, beta + (size_t)l * HDIM,
                nullptr, batch, pool, total4);
        }
    }

    // ---- head ----
    head_kernel<<<NGRAPH, 128>>>(pool, cnt, Wp1, bp1, Wp2, bp2, out);
}

// round 11
// speedup vs baseline: 3.1134x; 1.0925x over previous
#include <cuda_runtime.h>
#include <cuda_fp16.h>
#include <cstdint>

// ---------------- constants (problem-fixed) ----------------
#define NNODES 100000
#define NEDGES 300000
#define DIN    128
#define HDIM   256
#define H2     512
#define NLAYER 4
#define NGRAPH 512
#define BN_EPS 1e-5f

#define SCAN_B 1024
#define NBLK   ((NNODES + SCAN_B - 1) / SCAN_B)   // 98

// ---------------- scratch (device globals; no allocation allowed) ----------------
__device__ __half g_x16[NNODES * DIN];     // input features, fp16
__device__ __half g_h16[NNODES * HDIM];    // node features, fp16
__device__ __half g_agg16[NNODES * HDIM];  // (1+eps)h + neighbor sum, fp16
__device__ __half g_z1[NNODES * H2];       // MLP hidden, fp16
__device__ __half g_z2[NNODES * HDIM];     // MLP out (pre-BN), fp16
__device__ float g_stats[2 * HDIM];        // [sums | sumsq]
__device__ float g_pool[NGRAPH * HDIM];    // per-graph sums
__device__ float g_cnt[NGRAPH];            // per-graph counts
// CSR by destination
__device__ int g_deg[NNODES];
__device__ int g_rowptr[NNODES + 1];
__device__ int g_cursor[NNODES];
__device__ int g_ssrc[NEDGES];
__device__ int g_bsum[NBLK];
__device__ int g_boff[NBLK];

// converted weights: transposed [N][K], fp16
#define WIN_OFF  0
#define W1_OFF   (256 * 128)
#define W2_OFF   (W1_OFF + NLAYER * 512 * 256)
#define WT_TOTAL (W2_OFF + NLAYER * 256 * 512)
__device__ __align__(16) __half g_wh[WT_TOTAL];

// ---------------- helpers ----------------
__device__ __forceinline__ uint32_t smem_u32(const void* p) {
    uint32_t a;
    asm("{ .reg .u64 t; cvta.to.shared.u64 t, %1; cvt.u32.u64 %0, t; }" : "=r"(a) : "l"(p));
    return a;
}
__device__ __forceinline__ uint32_t pkh(float a, float b) {
    __half2 t; t.x = __float2half(a); t.y = __float2half(b);
    return *reinterpret_cast<uint32_t*>(&t);
}
__device__ __forceinline__ uint32_t sw128(uint32_t off) {
    return off ^ ((off >> 3) & 0x70);
}
__device__ __forceinline__ void ldm4(uint32_t* r, uint32_t addr) {
    asm volatile("ldmatrix.sync.aligned.m8n8.x4.shared.b16 {%0,%1,%2,%3}, [%4];"
                 : "=r"(r[0]), "=r"(r[1]), "=r"(r[2]), "=r"(r[3]) : "r"(addr));
}
__device__ __forceinline__ void mma16816(float* c, const uint32_t* a, const uint32_t* b) {
    asm volatile("mma.sync.aligned.m16n8k16.row.col.f32.f16.f16.f32 "
                 "{%0,%1,%2,%3}, {%4,%5,%6,%7}, {%8,%9}, {%0,%1,%2,%3};"
                 : "+f"(c[0]), "+f"(c[1]), "+f"(c[2]), "+f"(c[3])
                 : "r"(a[0]), "r"(a[1]), "r"(a[2]), "r"(a[3]), "r"(b[0]), "r"(b[1]));
}

// smem stage: 128 rows x 128B (SW128) per operand. A(16K) B(16K) = 32KB/stage, 3 stages.
#define T_A    0
#define T_B    16384
#define STAGE  32768
#define NSTG   3
#define SMEMB  (NSTG * STAGE + 256)

// ---------------- tensor-core GEMM via mma.sync fp16 ----------------
// C[M,N] = act(A[M,K]fp16 @ W[K,N] + bias); W fp16 [N][K]; A fp16 row-major.
// Block tile 128x128, 128 threads: 4 warps (2x2), warp tile 64x64, K-chunk 64.
// 3-stage cp.async pipeline (race-free), 2 CTAs/SM.
// EPI: 1 = bias+relu -> fp16 C; 3 = bias -> fp16 C + fused fp32 BN stats.
template <int EPI>
__global__ __launch_bounds__(128, 2)
void tc_gemm(const __half* __restrict__ A, const __half* __restrict__ Bh,
             const float* __restrict__ bias, __half* __restrict__ C,
             float* __restrict__ stats, int M, int N, int K)
{
    extern __shared__ __align__(16) char smraw[];
    const uint32_t sb = (smem_u32(smraw) + 127) & ~127u;

    const int tid = threadIdx.x;
    const int lane = tid & 31, wid = tid >> 5;
    const int wm = (wid & 1) * 64;       // 2 warps in M
    const int wn = (wid >> 1) * 64;      // 2 warps in N
    const int bm = blockIdx.y * 128, bn = blockIdx.x * 128;
    const int nc = K / 64;

    float acc[4][8][4];
#pragma unroll
    for (int i = 0; i < 4; i++)
#pragma unroll
        for (int j = 0; j < 8; j++)
#pragma unroll
            for (int q = 0; q < 4; q++) acc[i][j][q] = 0.f;

// issue one stage (chunk cc) of A+B loads: 8 x 16B segments each per thread
#define ISSUE_STAGE(cc, stg)                                                              \
    do {                                                                                  \
        _Pragma("unroll")                                                                 \
        for (int j = 0; j < 8; j++) {                                                     \
            int s = tid + 128 * j;                                                        \
            int row = s >> 3, seg = s & 7;                                                \
            uint32_t d = sw128((uint32_t)row * 128 + seg * 16);                           \
            int ra = bm + row; if (ra >= M) ra = M - 1;                                   \
            const __half* pa = A + (size_t)ra * K + (cc) * 64 + seg * 8;                  \
            asm volatile("cp.async.ca.shared.global [%0], [%1], 16;"                      \
                         :: "r"((stg) + T_A + d), "l"(pa));                               \
            const __half* pb = Bh + (size_t)(bn + row) * K + (cc) * 64 + seg * 8;         \
            asm volatile("cp.async.ca.shared.global [%0], [%1], 16;"                      \
                         :: "r"((stg) + T_B + d), "l"(pb));                               \
        }                                                                                 \
        asm volatile("cp.async.commit_group;");                                           \
    } while (0)

    // ---- prologue ----
    ISSUE_STAGE(0, sb);
    if (nc > 1) ISSUE_STAGE(1, sb + STAGE);
    if (nc > 1) { asm volatile("cp.async.wait_group 1;"); }
    else        { asm volatile("cp.async.wait_group 0;"); }
    __syncthreads();    // stage 0 ready for all warps

    // ldmatrix per-lane address components (128B rows)
    const uint32_t a_ro = (uint32_t)(lane & 15) * 128 + (uint32_t)(lane >> 4) * 16;
    const int brow = (lane & 7) + ((lane >> 4) << 3);
    const uint32_t b_ko = (uint32_t)((lane >> 3) & 1) * 16;

    for (int c = 0; c < nc; c++) {
        const uint32_t st0 = sb + (uint32_t)(c % NSTG) * STAGE;

        // ---- compute chunk c: 4 k16 steps ----
#pragma unroll
        for (int ks = 0; ks < 4; ks++) {
            uint32_t ahf[4][4], bhf[4][4];
#pragma unroll
            for (int mt = 0; mt < 4; mt++) {
                uint32_t off = (uint32_t)(wm + mt * 16) * 128 + a_ro + ks * 32;
                ldm4(ahf[mt], st0 + T_A + sw128(off));
            }
#pragma unroll
            for (int g = 0; g < 4; g++) {
                uint32_t off = (uint32_t)(wn + g * 16 + brow) * 128 + ks * 32 + b_ko;
                ldm4(bhf[g], st0 + T_B + sw128(off));
            }
#pragma unroll
            for (int mt = 0; mt < 4; mt++)
#pragma unroll
                for (int g = 0; g < 4; g++) {
                    mma16816(acc[mt][2 * g],     ahf[mt], &bhf[g][0]);
                    mma16816(acc[mt][2 * g + 1], ahf[mt], &bhf[g][2]);
                }
        }

        if (c + 1 < nc) {
            // barrier 1: every warp done with compute(c) — stage (c+2)%3 == (c-1)%3 free
            __syncthreads();
            if (c + 2 < nc) {
                ISSUE_STAGE(c + 2, sb + (uint32_t)((c + 2) % NSTG) * STAGE);
                asm volatile("cp.async.wait_group 1;");
            } else {
                asm volatile("cp.async.wait_group 0;");
            }
            // barrier 2: stage c+1 data visible to all warps
            __syncthreads();
        }
    }

    // ---- epilogue ----
    float* ssum = reinterpret_cast<float*>(smraw);        // [128]
    float* ssq  = reinterpret_cast<float*>(smraw) + 128;  // [128]
    if (EPI == 3) {
        __syncthreads();   // all warps done reading smem stages (overlaps stats area)
        ssum[tid] = 0.f;
        ssq[tid] = 0.f;
        __syncthreads();
    }

#pragma unroll
    for (int mt = 0; mt < 4; mt++) {
        int r0 = bm + wm + mt * 16 + (lane >> 2);
        int r1 = r0 + 8;
#pragma unroll
        for (int nt = 0; nt < 8; nt++) {
            int col = bn + wn + nt * 8 + (lane & 3) * 2;
            float2 bv = *reinterpret_cast<const float2*>(&bias[col]);
            float v0 = acc[mt][nt][0] + bv.x;
            float v1 = acc[mt][nt][1] + bv.y;
            float v2 = acc[mt][nt][2] + bv.x;
            float v3 = acc[mt][nt][3] + bv.y;
            if (EPI == 1) {
                v0 = fmaxf(v0, 0.f); v1 = fmaxf(v1, 0.f);
                v2 = fmaxf(v2, 0.f); v3 = fmaxf(v3, 0.f);
            }
            bool k0 = r0 < M, k1 = r1 < M;
            if (k0) *reinterpret_cast<uint32_t*>(&C[(size_t)r0 * N + col]) = pkh(v0, v1);
            if (k1) *reinterpret_cast<uint32_t*>(&C[(size_t)r1 * N + col]) = pkh(v2, v3);
            if (EPI == 3) {
                float a0 = (k0 ? v0 : 0.f) + (k1 ? v2 : 0.f);
                float a1 = (k0 ? v1 : 0.f) + (k1 ? v3 : 0.f);
                float q0 = (k0 ? v0 * v0 : 0.f) + (k1 ? v2 * v2 : 0.f);
                float q1 = (k0 ? v1 * v1 : 0.f) + (k1 ? v3 * v3 : 0.f);
#pragma unroll
                for (int off = 16; off >= 4; off >>= 1) {
                    a0 += __shfl_xor_sync(0xffffffffu, a0, off);
                    a1 += __shfl_xor_sync(0xffffffffu, a1, off);
                    q0 += __shfl_xor_sync(0xffffffffu, q0, off);
                    q1 += __shfl_xor_sync(0xffffffffu, q1, off);
                }
                if (lane < 4) {
                    int lc = wn + nt * 8 + lane * 2;
                    atomicAdd(&ssum[lc], a0);
                    atomicAdd(&ssum[lc + 1], a1);
                    atomicAdd(&ssq[lc], q0);
                    atomicAdd(&ssq[lc + 1], q1);
                }
            }
        }
    }
    if (EPI == 3) {
        __syncthreads();
        atomicAdd(&stats[bn + tid], ssum[tid]);
        atomicAdd(&stats[HDIM + bn + tid], ssq[tid]);
    }
}

// ---------------- input conversion: x fp32 -> fp16 ----------------
__global__ void conv_x(const float4* __restrict__ x, uint2* __restrict__ x16, int total4)
{
    int i = blockIdx.x * blockDim.x + threadIdx.x;
    if (i >= total4) return;
    float4 v = x[i];
    uint2 p;
    p.x = pkh(v.x, v.y);
    p.y = pkh(v.z, v.w);
    x16[i] = p;
}

// ---------------- all-weight conversion (one launch) ----------------
#define NW_IN (128 * 256)
#define NW_1  (256 * 512)
#define NW_2  (512 * 256)
__global__ void conv_w_all(const float* __restrict__ W_in, const float* __restrict__ W1,
                           const float* __restrict__ W2, __half* __restrict__ wh)
{
    int idx = blockIdx.x * blockDim.x + threadIdx.x;
    if (idx < NW_IN) {
        int n = idx / 128, k = idx % 128;
        wh[WIN_OFF + idx] = __float2half(W_in[(size_t)k * 256 + n]);
    } else if (idx < NW_IN + NLAYER * NW_1) {
        int t = idx - NW_IN;
        int l = t / NW_1, r = t % NW_1;
        int n = r / 256, k = r % 256;
        wh[W1_OFF + t] = __float2half(W1[(size_t)l * NW_1 + (size_t)k * 512 + n]);
    } else if (idx < NW_IN + NLAYER * (NW_1 + NW_2)) {
        int t = idx - NW_IN - NLAYER * NW_1;
        int l = t / NW_2, r = t % NW_2;
        int n = r / 512, k = r % 512;
        wh[W2_OFF + t] = __float2half(W2[(size_t)l * NW_2 + (size_t)k * 256 + n]);
    }
}

// ---------------- CSR build ----------------
__global__ void hist_kernel(const int* __restrict__ dst, int* __restrict__ deg, int E)
{
    int i = blockIdx.x * blockDim.x + threadIdx.x;
    if (i < E) atomicAdd(&deg[__ldg(&dst[i])], 1);
}

// phase 1: per-block inclusive scan; writes rowptr[i+1] (local) + block total
__global__ void scan_block(const int* __restrict__ deg, int* __restrict__ rowptr,
                           int* __restrict__ bsum)
{
    __shared__ int buf[SCAN_B];
    int tid = threadIdx.x;
    int gi = blockIdx.x * SCAN_B + tid;
    int v = (gi < NNODES) ? deg[gi] : 0;
    buf[tid] = v;
    __syncthreads();
#pragma unroll
    for (int off = 1; off < SCAN_B; off <<= 1) {
        int t = (tid >= off) ? buf[tid - off] : 0;
        __syncthreads();
        buf[tid] += t;
        __syncthreads();
    }
    if (gi < NNODES) rowptr[gi + 1] = buf[tid];
    if (tid == SCAN_B - 1) bsum[blockIdx.x] = buf[tid];
}

// phase 2: exclusive scan of NBLK block totals (one small block)
__global__ void scan_tops(const int* __restrict__ bsum, int* __restrict__ boff)
{
    __shared__ int buf[128];
    int tid = threadIdx.x;   // 128 >= NBLK
    buf[tid] = (tid < NBLK) ? bsum[tid] : 0;
    __syncthreads();
#pragma unroll
    for (int off = 1; off < 128; off <<= 1) {
        int t = (tid >= off) ? buf[tid - off] : 0;
        __syncthreads();
        buf[tid] += t;
        __syncthreads();
    }
    if (tid < NBLK) boff[tid] = (tid == 0) ? 0 : buf[tid - 1];
}

// phase 3: add block offsets
__global__ void scan_add(int* __restrict__ rowptr, const int* __restrict__ boff)
{
    int gi = blockIdx.x * SCAN_B + threadIdx.x;
    if (gi < NNODES) rowptr[gi + 1] += boff[blockIdx.x];
    if (gi == 0) rowptr[0] = 0;
}

__global__ void fill_kernel(const int* __restrict__ src, const int* __restrict__ dst,
                            int* __restrict__ cursor, int* __restrict__ ssrc, int E)
{
    int i = blockIdx.x * blockDim.x + threadIdx.x;
    if (i >= E) return;
    int pos = atomicAdd(&cursor[__ldg(&dst[i])], 1);
    ssrc[pos] = __ldg(&src[i]);
}

// ---------------- aggregate: agg16[d] = fp16((1+eps)*h[d] + sum_{src->d} h[src]) ----------------
__global__ void aggregate_kernel(const __half* __restrict__ h, const int* __restrict__ rowptr,
                                 const int* __restrict__ ssrc, const float* __restrict__ epsp,
                                 __half* __restrict__ agg)
{
    int warp = (blockIdx.x * blockDim.x + threadIdx.x) >> 5;
    int lane = threadIdx.x & 31;
    if (warp >= NNODES) return;
    int beg = __ldg(&rowptr[warp]);
    int end = __ldg(&rowptr[warp + 1]);
    float e = 1.0f + __ldg(epsp);

    float a[8];
    {
        uint4 v = __ldg(reinterpret_cast<const uint4*>(&h[(size_t)warp * HDIM + lane * 8]));
        const __half2* p = reinterpret_cast<const __half2*>(&v);
#pragma unroll
        for (int q = 0; q < 4; q++) {
            float2 f = __half22float2(p[q]);
            a[2 * q] = e * f.x;
            a[2 * q + 1] = e * f.y;
        }
    }
    int j = beg;
    for (; j + 1 < end; j += 2) {
        int s0 = __ldg(&ssrc[j]);
        int s1 = __ldg(&ssrc[j + 1]);
        uint4 v0 = __ldg(reinterpret_cast<const uint4*>(&h[(size_t)s0 * HDIM + lane * 8]));
        uint4 v1 = __ldg(reinterpret_cast<const uint4*>(&h[(size_t)s1 * HDIM + lane * 8]));
        const __half2* p0 = reinterpret_cast<const __half2*>(&v0);
        const __half2* p1 = reinterpret_cast<const __half2*>(&v1);
#pragma unroll
        for (int q = 0; q < 4; q++) {
            float2 f0 = __half22float2(p0[q]);
            float2 f1 = __half22float2(p1[q]);
            a[2 * q] += f0.x + f1.x;
            a[2 * q + 1] += f0.y + f1.y;
        }
    }
    if (j < end) {
        int s0 = __ldg(&ssrc[j]);
        uint4 v0 = __ldg(reinterpret_cast<const uint4*>(&h[(size_t)s0 * HDIM + lane * 8]));
        const __half2* p0 = reinterpret_cast<const __half2*>(&v0);
#pragma unroll
        for (int q = 0; q < 4; q++) {
            float2 f0 = __half22float2(p0[q]);
            a[2 * q] += f0.x;
            a[2 * q + 1] += f0.y;
        }
    }
    uint4 o;
    uint32_t* ow = reinterpret_cast<uint32_t*>(&o);
#pragma unroll
    for (int q = 0; q < 4; q++) ow[q] = pkh(a[2 * q], a[2 * q + 1]);
    *reinterpret_cast<uint4*>(&agg[(size_t)warp * HDIM + lane * 8]) = o;
}

// ---------------- BN apply + relu (z2 fp16) ----------------
// POOL=0: write h16 (fp16). POOL=1: per-graph pool atomics only.
template <int POOL>
__global__ void bn_apply_kernel(const uint2* __restrict__ z, const float* __restrict__ stats,
                                const float* __restrict__ gamma, const float* __restrict__ beta,
                                uint2* __restrict__ h16,
                                const int* __restrict__ batch, float* __restrict__ pool,
                                int total4)
{
    int i = blockIdx.x * blockDim.x + threadIdx.x;
    if (i >= total4) return;
    int c = (i << 2) & (HDIM - 1);
    const float invN = 1.0f / (float)NNODES;
    float4 s = *reinterpret_cast<const float4*>(&stats[c]);
    float4 q = *reinterpret_cast<const float4*>(&stats[HDIM + c]);
    float4 g = *reinterpret_cast<const float4*>(&gamma[c]);
    float4 b = *reinterpret_cast<const float4*>(&beta[c]);
    uint2 zp = z[i];
    float2 z01 = __half22float2(*reinterpret_cast<const __half2*>(&zp.x));
    float2 z23 = __half22float2(*reinterpret_cast<const __half2*>(&zp.y));
    float4 r;
    {
        float mu = s.x * invN, var = q.x * invN - mu * mu;
        r.x = fmaxf((z01.x - mu) * (g.x * rsqrtf(var + BN_EPS)) + b.x, 0.f);
    }
    {
        float mu = s.y * invN, var = q.y * invN - mu * mu;
        r.y = fmaxf((z01.y - mu) * (g.y * rsqrtf(var + BN_EPS)) + b.y, 0.f);
    }
    {
        float mu = s.z * invN, var = q.z * invN - mu * mu;
        r.z = fmaxf((z23.x - mu) * (g.z * rsqrtf(var + BN_EPS)) + b.z, 0.f);
    }
    {
        float mu = s.w * invN, var = q.w * invN - mu * mu;
        r.w = fmaxf((z23.y - mu) * (g.w * rsqrtf(var + BN_EPS)) + b.w, 0.f);
    }
    if (POOL == 0) {
        uint2 p;
        p.x = pkh(r.x, r.y);
        p.y = pkh(r.z, r.w);
        h16[i] = p;
    } else {
        int node = i >> 6;
        int gidx = __ldg(&batch[node]);
        float* o = &pool[(size_t)gidx * HDIM + c];
        atomicAdd(o + 0, r.x);
        atomicAdd(o + 1, r.y);
        atomicAdd(o + 2, r.z);
        atomicAdd(o + 3, r.w);
    }
}

// ---------------- per-graph node counts ----------------
__global__ void count_kernel(const int* __restrict__ batch, float* __restrict__ cnt, int n)
{
    int i = blockIdx.x * blockDim.x + threadIdx.x;
    if (i < n) atomicAdd(&cnt[__ldg(&batch[i])], 1.0f);
}

// ---------------- predictor head ----------------
__global__ void head_kernel(const float* __restrict__ pooled, const float* __restrict__ cnt,
                            const float* __restrict__ Wp1, const float* __restrict__ bp1,
                            const float* __restrict__ Wp2, const float* __restrict__ bp2,
                            float* __restrict__ out)
{
    __shared__ float sp[HDIM];
    __shared__ float red[128];
    int g = blockIdx.x;
    int tid = threadIdx.x;   // 128 threads
    float inv = 1.0f / fmaxf(__ldg(&cnt[g]), 1.0f);
    for (int k = tid; k < HDIM; k += 128)
        sp[k] = pooled[(size_t)g * HDIM + k] * inv;
    __syncthreads();

    float s = __ldg(&bp1[tid]);
#pragma unroll 4
    for (int k = 0; k < HDIM; k++)
        s = fmaf(sp[k], __ldg(&Wp1[k * 128 + tid]), s);
    s = fmaxf(s, 0.f);
    float t = s * __ldg(&Wp2[tid]);

    red[tid] = t;
    __syncthreads();
    for (int off = 64; off > 0; off >>= 1) {
        if (tid < off) red[tid] += red[tid + off];
        __syncthreads();
    }
    if (tid == 0) out[g] = red[0] + __ldg(&bp2[0]);
}

// ---------------- host launch ----------------
static void* sym_addr(const void* symbol)
{
    void* p = nullptr;
    cudaGetSymbolAddress(&p, symbol);
    return p;
}

extern "C" void kernel_launch(void* const* d_in, const int* in_sizes, int n_in,
                              void* d_out, int out_size)
{
    const float* x      = (const float*)d_in[0];
    const int*   ei     = (const int*)d_in[1];
    const int*   batch  = (const int*)d_in[2];
    const float* W_in   = (const float*)d_in[3];
    const float* b_in   = (const float*)d_in[4];
    const float* eps    = (const float*)d_in[5];
    const float* W1     = (const float*)d_in[6];
    const float* b1     = (const float*)d_in[7];
    const float* W2     = (const float*)d_in[8];
    const float* b2     = (const float*)d_in[9];
    const float* gamma  = (const float*)d_in[10];
    const float* beta   = (const float*)d_in[11];
    const float* Wp1    = (const float*)d_in[12];
    const float* bp1    = (const float*)d_in[13];
    const float* Wp2    = (const float*)d_in[14];
    const float* bp2    = (const float*)d_in[15];
    float* out = (float*)d_out;

    const int E = in_sizes[1] / 2;
    const int* src = ei;
    const int* dst = ei + E;

    __half* x16   = (__half*)sym_addr(g_x16);
    __half* h16   = (__half*)sym_addr(g_h16);
    __half* agg16 = (__half*)sym_addr(g_agg16);
    __half* z1    = (__half*)sym_addr(g_z1);
    __half* z2    = (__half*)sym_addr(g_z2);
    float* stats  = (float*)sym_addr(g_stats);
    float* pool   = (float*)sym_addr(g_pool);
    float* cnt    = (float*)sym_addr(g_cnt);
    __half* wh    = (__half*)sym_addr(g_wh);
    int* deg      = (int*)sym_addr(g_deg);
    int* rowptr   = (int*)sym_addr(g_rowptr);
    int* cursor   = (int*)sym_addr(g_cursor);
    int* ssrc     = (int*)sym_addr(g_ssrc);
    int* bsum     = (int*)sym_addr(g_bsum);
    int* boff     = (int*)sym_addr(g_boff);

    cudaFuncSetAttribute((const void*)tc_gemm<1>, cudaFuncAttributeMaxDynamicSharedMemorySize, SMEMB);
    cudaFuncSetAttribute((const void*)tc_gemm<3>, cudaFuncAttributeMaxDynamicSharedMemorySize, SMEMB);

    const int M = NNODES;
    const int mt = (M + 127) / 128;    // 782
    const int totalH = M * HDIM;
    const int total4 = totalH / 4;

    // ---- weight + input prep ----
    {
        int tot = NW_IN + NLAYER * (NW_1 + NW_2);
        conv_w_all<<<(tot + 255) / 256, 256>>>(W_in, W1, W2, wh);
    }
    conv_x<<<(M * DIN / 4 + 255) / 256, 256>>>((const float4*)x, (uint2*)x16, M * DIN / 4);

    // ---- CSR build (by dst); 3-phase parallel scan ----
    cudaMemsetAsync(deg, 0, NNODES * sizeof(int));
    hist_kernel<<<(E + 255) / 256, 256>>>(dst, deg, E);
    scan_block<<<NBLK, SCAN_B>>>(deg, rowptr, bsum);
    scan_tops<<<1, 128>>>(bsum, boff);
    scan_add<<<NBLK, SCAN_B>>>(rowptr, boff);
    cudaMemcpyAsync(cursor, rowptr, NNODES * sizeof(int), cudaMemcpyDeviceToDevice);
    fill_kernel<<<(E + 255) / 256, 256>>>(src, dst, cursor, ssrc, E);

    // ---- input projection: h16 = relu(x16 @ W_in + b_in) ----
    tc_gemm<1><<<dim3(2, mt), 128, SMEMB>>>(x16, wh + WIN_OFF, b_in, h16, nullptr,
                                            M, HDIM, DIN);

    for (int l = 0; l < NLAYER; l++) {
        // agg16 = (1+eps_l)*h + gather-sum
        aggregate_kernel<<<(NNODES * 32 + 255) / 256, 256>>>(h16, rowptr, ssrc, eps + l, agg16);
        // z1 = relu(agg16 @ W1_l + b1_l) -> fp16
        tc_gemm<1><<<dim3(4, mt), 128, SMEMB>>>(agg16, wh + W1_OFF + (size_t)l * H2 * HDIM,
                                                b1 + (size_t)l * H2, z1, nullptr,
                                                M, H2, HDIM);
        // z2 = z1 @ W2_l + b2_l (fp16) + fused fp32 BN stats
        cudaMemsetAsync(stats, 0, 2 * HDIM * sizeof(float));
        tc_gemm<3><<<dim3(2, mt), 128, SMEMB>>>(z1, wh + W2_OFF + (size_t)l * HDIM * H2,
                                                b2 + (size_t)l * HDIM, z2, stats,
                                                M, HDIM, H2);
        // BN apply + relu
        if (l + 1 < NLAYER) {
            bn_apply_kernel<0><<<(total4 + 255) / 256, 256>>>(
                (const uint2*)z2, stats, gamma + (size_t)l * HDIM, beta + (size_t)l * HDIM,
                (uint2*)h16, nullptr, nullptr, total4);
        } else {
            cudaMemsetAsync(pool, 0, NGRAPH * HDIM * sizeof(float));
            cudaMemsetAsync(cnt, 0, NGRAPH * sizeof(float));
            count_kernel<<<(M + 255) / 256, 256>>>(batch, cnt, M);
            bn_apply_kernel<1><<<(total4 + 255) / 256, 256>>>(
                (const uint2*)z2, stats, gamma + (size_t)l * HDIM, beta + (size_t)l * HDIM,
                nullptr, batch, pool, total4);
        }
    }

    // ---- head ----
    head_kernel<<<NGRAPH, 128>>>(pool, cnt, Wp1, bp1, Wp2, bp2, out);
}